// round 5
// baseline (speedup 1.0000x reference)
#include <cuda_runtime.h>
#include <math.h>
#include <stdint.h>

// Problem constants
constexpr int B  = 4;
constexpr int T  = 2048;
constexpr int D  = 768;
constexpr int H  = 12;
constexpr int HD = 64;
constexpr int BT = B * T;          // 8192
constexpr int NQKV = 3 * D;        // 2304
constexpr float EPS  = 1e-4f;
constexpr float GAIN = 1.8402f;

constexpr int PAD  = 36;           // GEMM k-chunk stride: (4g+c) mod 32 unique
constexpr int APAD = 68;           // attention 64-wide tile stride (4 mod 32; 272B = 16*17)
constexpr int KC   = 32;           // GEMM k-chunk
constexpr int NC   = D / KC;       // 24 chunks

// SMEM stage sizes (uint32 units) for GEMM kernels
constexpr int GA_SZ = 128 * PAD;           // 4608
constexpr int GSTAGE = 2 * GA_SZ;          // A + B per stage = 9216
constexpr int GEMM_SMEM = 2 * GSTAGE * 4;  // 73728 B

// Scratch (allocation-free rule: __device__ globals). All tf32 bit patterns.
__device__ uint32_t g_xt[BT * D];
__device__ uint32_t g_wn_qkv[NQKV * D];
__device__ uint32_t g_wn_out[D * D];
__device__ uint32_t g_Q[B * H * T * HD];
__device__ uint32_t g_K[B * H * T * HD];
__device__ uint32_t g_V[B * H * T * HD];
__device__ uint32_t g_att[BT * D];
__device__ float    g_mag[BT];

__device__ __forceinline__ uint32_t tf32(float x) {
    uint32_t u; asm("cvt.rna.tf32.f32 %0, %1;" : "=r"(u) : "f"(x)); return u;
}
__device__ __forceinline__ float fast_sigmoid8(float s) {
    // sigmoid(s/8) = 0.5*tanh(s/16) + 0.5, single MUFU op
    float t; asm("tanh.approx.f32 %0, %1;" : "=f"(t) : "f"(s * 0.0625f));
    return fmaf(0.5f, t, 0.5f);
}
__device__ __forceinline__ void mma8(float c[4], const uint32_t a[4], const uint32_t b[2]) {
    asm volatile(
        "mma.sync.aligned.m16n8k8.row.col.f32.tf32.tf32.f32 "
        "{%0,%1,%2,%3}, {%4,%5,%6,%7}, {%8,%9}, {%0,%1,%2,%3};"
        : "+f"(c[0]), "+f"(c[1]), "+f"(c[2]), "+f"(c[3])
        : "r"(a[0]), "r"(a[1]), "r"(a[2]), "r"(a[3]), "r"(b[0]), "r"(b[1]));
}
__device__ __forceinline__ uint32_t saddr(const void* p) {
    return (uint32_t)__cvta_generic_to_shared(p);
}
__device__ __forceinline__ void cp16(uint32_t s, const void* g) {
    asm volatile("cp.async.cg.shared.global [%0], [%1], 16;" :: "r"(s), "l"(g));
}
__device__ __forceinline__ void cp_commit() {
    asm volatile("cp.async.commit_group;" ::: "memory");
}
template <int N>
__device__ __forceinline__ void cp_wait() {
    asm volatile("cp.async.wait_group %0;" :: "n"(N) : "memory");
}

// ---------------------------------------------------------------------------
// Kernel 1: weight row-norm -> tf32; x -> tf32 copy + per-token magnitude.
// ---------------------------------------------------------------------------
__global__ void __launch_bounds__(256) prep_kernel(const float* __restrict__ x,
                                                   const float* __restrict__ qkv_w,
                                                   const float* __restrict__ out_w) {
    const int r = blockIdx.x;
    const float* src;
    uint32_t* dst;
    float* magdst = nullptr;
    bool donorm = true;
    if (r < NQKV) {
        src = qkv_w + (size_t)r * D;  dst = g_wn_qkv + (size_t)r * D;
    } else if (r < NQKV + D) {
        src = out_w + (size_t)(r - NQKV) * D;  dst = g_wn_out + (size_t)(r - NQKV) * D;
    } else {
        const int tr = r - (NQKV + D);
        src = x + (size_t)tr * D;  dst = g_xt + (size_t)tr * D;
        magdst = g_mag + tr;  donorm = false;
    }
    const int tid = threadIdx.x;
    float v[3];
    float s = 0.f;
#pragma unroll
    for (int i = 0; i < 3; i++) { v[i] = src[tid + i * 256]; s += v[i] * v[i]; }
#pragma unroll
    for (int o = 16; o > 0; o >>= 1) s += __shfl_xor_sync(0xffffffffu, s, o);
    __shared__ float red[8];
    __shared__ float stot;
    if ((tid & 31) == 0) red[tid >> 5] = s;
    __syncthreads();
    if (tid == 0) {
        float t = red[0];
#pragma unroll
        for (int i = 1; i < 8; i++) t += red[i];
        stot = t;
    }
    __syncthreads();
    const float tot = stot;
    if (donorm) {
        const float inv = 1.0f / (sqrtf(tot) + EPS);
#pragma unroll
        for (int i = 0; i < 3; i++) dst[tid + i * 256] = tf32(v[i] * inv);
    } else {
#pragma unroll
        for (int i = 0; i < 3; i++) dst[tid + i * 256] = tf32(v[i]);
        if (tid == 0) magdst[0] = sqrtf(tot) * (1.0f / sqrtf((float)D));
    }
}

// ---------------------------------------------------------------------------
// tf32 GEMM core: C[128 x 128] = A[m0..][:] * W[n0..][:]^T
// 8 warps (4m x 2n), warp tile 32x64. cp.async 2-stage pipeline.
// ---------------------------------------------------------------------------
__device__ __forceinline__ void gemm_core(const uint32_t* __restrict__ A,
                                          const uint32_t* __restrict__ W,
                                          int m0, int n0, uint32_t* sm,
                                          float (&acc)[2][8][4], int tid) {
    const int lane = tid & 31, warp = tid >> 5;
    const int wm = warp >> 1, wn = warp & 1;
    const int g = lane >> 2, c = lane & 3;
    const uint32_t* Ab = A + (size_t)m0 * D;
    const uint32_t* Wb = W + (size_t)n0 * D;
    const int sr = tid >> 3, scol = (tid & 7) * 4;

    const uint32_t smA0 = saddr(sm);
    auto load_chunk = [&](int s, int k0) {
        const uint32_t baseA = smA0 + (uint32_t)(s * GSTAGE) * 4;
        const uint32_t baseB = baseA + (uint32_t)GA_SZ * 4;
#pragma unroll
        for (int i = 0; i < 4; i++) {
            const int row = sr + i * 32;
            cp16(baseA + (uint32_t)(row * PAD + scol) * 4, Ab + (size_t)row * D + k0 + scol);
        }
#pragma unroll
        for (int i = 0; i < 4; i++) {
            const int row = sr + i * 32;
            cp16(baseB + (uint32_t)(row * PAD + scol) * 4, Wb + (size_t)row * D + k0 + scol);
        }
    };

    load_chunk(0, 0);
    cp_commit();
    for (int i = 0; i < NC; i++) {
        if (i + 1 < NC) {
            load_chunk((i + 1) & 1, (i + 1) * KC);
            cp_commit();
            cp_wait<1>();
        } else {
            cp_wait<0>();
        }
        __syncthreads();
        const uint32_t* As = sm + (i & 1) * GSTAGE;
        const uint32_t* Bs = As + GA_SZ;
#pragma unroll
        for (int ks = 0; ks < 4; ks++) {
            const int kk = ks * 8;
            uint32_t af[2][4], bf[8][2];
#pragma unroll
            for (int mt = 0; mt < 2; mt++) {
                const uint32_t* p = &As[(wm * 32 + mt * 16 + g) * PAD + kk + c];
                af[mt][0] = p[0];        af[mt][2] = p[4];
                af[mt][1] = p[8 * PAD];  af[mt][3] = p[8 * PAD + 4];
            }
#pragma unroll
            for (int nt = 0; nt < 8; nt++) {
                const uint32_t* p = &Bs[(wn * 64 + nt * 8 + g) * PAD + kk + c];
                bf[nt][0] = p[0]; bf[nt][1] = p[4];
            }
#pragma unroll
            for (int mt = 0; mt < 2; mt++)
#pragma unroll
                for (int nt = 0; nt < 8; nt++) mma8(acc[mt][nt], af[mt], bf[nt]);
        }
        __syncthreads();
    }
}

// ---------------------------------------------------------------------------
// Kernel 2: qkv GEMM + warp-local per-head q/k RMS-normalize + tf32 scatter.
// grid: (2304/128, 8192/128). Each warp's 64-wide n-extent == one head.
// ---------------------------------------------------------------------------
__global__ void __launch_bounds__(256) qkv_mm() {
    extern __shared__ uint32_t sm[];
    const int n0 = blockIdx.x * 128, m0 = blockIdx.y * 128;
    const int tid = threadIdx.x, lane = tid & 31, warp = tid >> 5;
    const int wm = warp >> 1, wn = warp & 1, g = lane >> 2, c = lane & 3;

    float acc[2][8][4] = {};
    gemm_core(g_xt, g_wn_qkv, m0, n0, sm, acc, tid);

    const int which = n0 / D;                      // 0=q 1=k 2=v
    const int head = (n0 % D) / HD + wn;           // warp owns one full head
    const int b = m0 / T;
    uint32_t* dstb = (which == 0) ? g_Q : (which == 1) ? g_K : g_V;

#pragma unroll
    for (int mt = 0; mt < 2; mt++) {
        float sc[2] = {1.f, 1.f};
        if (which < 2) {
            float s0 = 0.f, s1 = 0.f;
#pragma unroll
            for (int nt = 0; nt < 8; nt++) {
                s0 += acc[mt][nt][0] * acc[mt][nt][0] + acc[mt][nt][1] * acc[mt][nt][1];
                s1 += acc[mt][nt][2] * acc[mt][nt][2] + acc[mt][nt][3] * acc[mt][nt][3];
            }
            s0 += __shfl_xor_sync(~0u, s0, 1); s0 += __shfl_xor_sync(~0u, s0, 2);
            s1 += __shfl_xor_sync(~0u, s1, 1); s1 += __shfl_xor_sync(~0u, s1, 2);
            sc[0] = 8.0f / (sqrtf(s0) + EPS);      // sqrt(HD)=8
            sc[1] = 8.0f / (sqrtf(s1) + EPS);
        }
#pragma unroll
        for (int rr = 0; rr < 2; rr++) {
            const int m = m0 + wm * 32 + mt * 16 + g + rr * 8;
            const int t = m & (T - 1);
            uint32_t* dp = dstb + (((size_t)(b * H + head)) * T + t) * HD;
#pragma unroll
            for (int nt = 0; nt < 8; nt++) {
                const int col = nt * 8 + 2 * c;
                uint2 v = make_uint2(tf32(acc[mt][nt][rr * 2] * sc[rr]),
                                     tf32(acc[mt][nt][rr * 2 + 1] * sc[rr]));
                *(uint2*)&dp[col] = v;
            }
        }
    }
}

// ---------------------------------------------------------------------------
// Kernel 3: fused sigmoid attention (R3 structure: static 34.8KB smem,
// LDG.128 -> STS staging of pre-converted tf32 K/V, tanh-based sigmoid).
// Block: 128 q-rows, 8 warps (16 rows x 64 cols). Q frags in registers.
// grid: (T/128, H, B)
// ---------------------------------------------------------------------------
__global__ void __launch_bounds__(256) attn_mma() {
    __shared__ __align__(16) uint32_t Ks[64 * APAD];
    __shared__ __align__(16) uint32_t Vs[64 * APAD];
    const int tid = threadIdx.x, lane = tid & 31, warp = tid >> 5;
    const int g = lane >> 2, c = lane & 3;
    const int q0 = blockIdx.x * 128;
    const int h = blockIdx.y, b = blockIdx.z;
    const size_t bh = ((size_t)(b * H + h)) * T;

    // Q fragments (16 rows x 64 k) persistent in registers (already tf32)
    uint32_t qf[8][4];
    {
        const uint32_t* Qg = g_Q + (bh + q0 + warp * 16) * HD;
#pragma unroll
        for (int kt = 0; kt < 8; kt++) {
            qf[kt][0] = Qg[(size_t)g * HD + kt * 8 + c];
            qf[kt][1] = Qg[(size_t)(g + 8) * HD + kt * 8 + c];
            qf[kt][2] = Qg[(size_t)g * HD + kt * 8 + c + 4];
            qf[kt][3] = Qg[(size_t)(g + 8) * HD + kt * 8 + c + 4];
        }
    }

    float oacc[8][4] = {};
    const int src0 = (lane & 28) | (c >> 1);
    const int src1 = src0 + 2;
    const bool odd = c & 1;

    for (int s0 = 0; s0 < T; s0 += 64) {
        __syncthreads();
        const uint32_t* Kg = g_K + (bh + s0) * HD;
        const uint32_t* Vg = g_V + (bh + s0) * HD;
#pragma unroll
        for (int i = 0; i < 4; i++) {
            const int l = tid + i * 256, r = l >> 4, cc = (l & 15) * 4;
            *(uint4*)&Ks[r * APAD + cc] = *(const uint4*)&Kg[(size_t)r * HD + cc];
            *(uint4*)&Vs[r * APAD + cc] = *(const uint4*)&Vg[(size_t)r * HD + cc];
        }
        __syncthreads();

        // S = Q K^T  (16 x 64 per warp)
        float sacc[8][4] = {};
#pragma unroll
        for (int ks = 0; ks < 8; ks++) {
            uint32_t bf[8][2];
#pragma unroll
            for (int nt = 0; nt < 8; nt++) {
                const uint32_t* p = &Ks[(nt * 8 + g) * APAD + ks * 8 + c];
                bf[nt][0] = p[0]; bf[nt][1] = p[4];
            }
#pragma unroll
            for (int nt = 0; nt < 8; nt++) mma8(sacc[nt], qf[ks], bf[nt]);
        }

        // sigmoid(S/8) via tanh.approx (1 MUFU op per element)
#pragma unroll
        for (int nt = 0; nt < 8; nt++)
#pragma unroll
            for (int j = 0; j < 4; j++)
                sacc[nt][j] = fast_sigmoid8(sacc[nt][j]);

        // O += P V  (C-frag -> A-frag via shuffles)
#pragma unroll
        for (int kt = 0; kt < 8; kt++) {
            uint32_t af[4];
            float w0 = __shfl_sync(~0u, sacc[kt][0], src0);
            float w1 = __shfl_sync(~0u, sacc[kt][1], src0);
            af[0] = tf32(odd ? w1 : w0);
            float w2 = __shfl_sync(~0u, sacc[kt][2], src0);
            float w3 = __shfl_sync(~0u, sacc[kt][3], src0);
            af[1] = tf32(odd ? w3 : w2);
            float x0 = __shfl_sync(~0u, sacc[kt][0], src1);
            float x1 = __shfl_sync(~0u, sacc[kt][1], src1);
            af[2] = tf32(odd ? x1 : x0);
            float x2 = __shfl_sync(~0u, sacc[kt][2], src1);
            float x3 = __shfl_sync(~0u, sacc[kt][3], src1);
            af[3] = tf32(odd ? x3 : x2);
#pragma unroll
            for (int nt = 0; nt < 8; nt++) {
                uint32_t bf2[2];
                const uint32_t* vp = &Vs[(kt * 8 + c) * APAD + nt * 8 + g];
                bf2[0] = vp[0]; bf2[1] = vp[4 * APAD];
                mma8(oacc[nt], af, bf2);
            }
        }
    }

    // Epilogue: out = mag * 8*cst*acc / (cst*||acc|| + eps), stored tf32
    const float cst = GAIN * rsqrtf((float)T);
#pragma unroll
    for (int rr = 0; rr < 2; rr++) {
        float s = 0.f;
#pragma unroll
        for (int nt = 0; nt < 8; nt++)
            s += oacc[nt][rr * 2] * oacc[nt][rr * 2] + oacc[nt][rr * 2 + 1] * oacc[nt][rr * 2 + 1];
        s += __shfl_xor_sync(~0u, s, 1);
        s += __shfl_xor_sync(~0u, s, 2);
        const int t = q0 + warp * 16 + g + rr * 8;
        const float n = cst * sqrtf(s);
        const float f = 8.0f * cst * g_mag[b * T + t] / (n + EPS);
        uint32_t* dp = g_att + ((size_t)b * T + t) * D + h * HD;
#pragma unroll
        for (int nt = 0; nt < 8; nt++)
            *(uint2*)&dp[nt * 8 + 2 * c] = make_uint2(tf32(oacc[nt][rr * 2] * f),
                                                      tf32(oacc[nt][rr * 2 + 1] * f));
    }
}

// ---------------------------------------------------------------------------
// Kernel 4: out-projection  y = att @ wn_out^T  (fp32 out)
// grid: (768/128, 8192/128)
// ---------------------------------------------------------------------------
__global__ void __launch_bounds__(256) proj_mm(float* __restrict__ out) {
    extern __shared__ uint32_t sm[];
    const int n0 = blockIdx.x * 128, m0 = blockIdx.y * 128;
    const int tid = threadIdx.x, lane = tid & 31, warp = tid >> 5;
    const int wm = warp >> 1, wn = warp & 1, g = lane >> 2, c = lane & 3;

    float acc[2][8][4] = {};
    gemm_core(g_att, g_wn_out, m0, n0, sm, acc, tid);

#pragma unroll
    for (int mt = 0; mt < 2; mt++) {
#pragma unroll
        for (int rr = 0; rr < 2; rr++) {
            const int m = m0 + wm * 32 + mt * 16 + g + rr * 8;
            float* dp = out + (size_t)m * D + n0 + wn * 64;
#pragma unroll
            for (int nt = 0; nt < 8; nt++) {
                const int col = nt * 8 + 2 * c;
                *(float2*)&dp[col] = make_float2(acc[mt][nt][rr * 2],
                                                 acc[mt][nt][rr * 2 + 1]);
            }
        }
    }
}

// ---------------------------------------------------------------------------
extern "C" void kernel_launch(void* const* d_in, const int* in_sizes, int n_in,
                              void* d_out, int out_size) {
    const float* x     = (const float*)d_in[0];
    const float* qkv_w = (const float*)d_in[1];
    const float* out_w = (const float*)d_in[2];

    cudaFuncSetAttribute(qkv_mm, cudaFuncAttributeMaxDynamicSharedMemorySize, GEMM_SMEM);
    cudaFuncSetAttribute(proj_mm, cudaFuncAttributeMaxDynamicSharedMemorySize, GEMM_SMEM);

    prep_kernel<<<NQKV + D + BT, 256>>>(x, qkv_w, out_w);
    qkv_mm<<<dim3(NQKV / 128, BT / 128), 256, GEMM_SMEM>>>();
    attn_mma<<<dim3(T / 128, H, B), 256>>>();
    proj_mm<<<dim3(D / 128, BT / 128), 256, GEMM_SMEM>>>((float*)d_out);
}

// round 6
// speedup vs baseline: 2.6098x; 2.6098x over previous
#include <cuda_runtime.h>
#include <cuda_fp16.h>
#include <math.h>
#include <stdint.h>

// Problem constants
constexpr int B  = 4;
constexpr int T  = 2048;
constexpr int D  = 768;
constexpr int H  = 12;
constexpr int HD = 64;
constexpr int BT = B * T;          // 8192
constexpr int NQKV = 3 * D;        // 2304
constexpr float EPS  = 1e-4f;
constexpr float GAIN = 1.8402f;

constexpr int Dh   = D / 2;        // 384 uint32 (half2) per row
constexpr int PAD  = 20;           // gemm chunk row stride (16 data + 4): (20g+c)%32 distinct
constexpr int APAD = 36;           // attn row stride (32 data + 4): (4g+c)%32 distinct
constexpr int KC   = 16;           // gemm k-chunk in uint32 (= 32 halfs)
constexpr int NC   = Dh / KC;      // 24 chunks

// Scratch (__device__ globals; fp16 storage packed as uint32 = half2)
__device__ uint32_t g_xh[BT * Dh];
__device__ uint32_t g_wq[NQKV * Dh];
__device__ uint32_t g_wo[D * Dh];
__device__ uint32_t g_Q[B * H * T * (HD / 2)];
__device__ uint32_t g_K[B * H * T * (HD / 2)];
__device__ __half   g_Vt[(size_t)B * H * HD * T];   // V transposed: [b][h][d][t]
__device__ uint32_t g_att[BT * Dh];
__device__ float    g_mag[BT];

__device__ __forceinline__ uint32_t h2(float lo, float hi) {
    uint32_t u;  // first asm source -> upper 16 bits
    asm("cvt.rn.f16x2.f32 %0, %1, %2;" : "=r"(u) : "f"(hi), "f"(lo));
    return u;
}
__device__ __forceinline__ float fast_sigmoid8(float s) {
    // sigmoid(s/8) = 0.5*tanh(s/16) + 0.5, single MUFU op
    float t; asm("tanh.approx.f32 %0, %1;" : "=f"(t) : "f"(s * 0.0625f));
    return fmaf(0.5f, t, 0.5f);
}
__device__ __forceinline__ void mma16(float c[4], const uint32_t a[4], const uint32_t b[2]) {
    asm volatile(
        "mma.sync.aligned.m16n8k16.row.col.f32.f16.f16.f32 "
        "{%0,%1,%2,%3}, {%4,%5,%6,%7}, {%8,%9}, {%0,%1,%2,%3};"
        : "+f"(c[0]), "+f"(c[1]), "+f"(c[2]), "+f"(c[3])
        : "r"(a[0]), "r"(a[1]), "r"(a[2]), "r"(a[3]), "r"(b[0]), "r"(b[1]));
}

// ---------------------------------------------------------------------------
// Kernel 1: weight row-norm -> fp16; x -> fp16 copy + per-token magnitude.
// One block per 768-length row. tid<192 handle one float4 each.
// ---------------------------------------------------------------------------
__global__ void __launch_bounds__(256) prep_kernel(const float* __restrict__ x,
                                                   const float* __restrict__ qkv_w,
                                                   const float* __restrict__ out_w) {
    const int r = blockIdx.x;
    const float* src;
    uint32_t* dst;
    float* magdst = nullptr;
    bool donorm = true;
    if (r < NQKV) {
        src = qkv_w + (size_t)r * D;  dst = g_wq + (size_t)r * Dh;
    } else if (r < NQKV + D) {
        src = out_w + (size_t)(r - NQKV) * D;  dst = g_wo + (size_t)(r - NQKV) * Dh;
    } else {
        const int tr = r - (NQKV + D);
        src = x + (size_t)tr * D;  dst = g_xh + (size_t)tr * Dh;
        magdst = g_mag + tr;  donorm = false;
    }
    const int tid = threadIdx.x;
    float4 f = make_float4(0.f, 0.f, 0.f, 0.f);
    if (tid < 192) f = ((const float4*)src)[tid];
    float s = f.x * f.x + f.y * f.y + f.z * f.z + f.w * f.w;
#pragma unroll
    for (int o = 16; o > 0; o >>= 1) s += __shfl_xor_sync(0xffffffffu, s, o);
    __shared__ float red[8];
    __shared__ float stot;
    if ((tid & 31) == 0) red[tid >> 5] = s;
    __syncthreads();
    if (tid == 0) {
        float t = red[0];
#pragma unroll
        for (int i = 1; i < 8; i++) t += red[i];
        stot = t;
    }
    __syncthreads();
    const float tot = stot;
    if (donorm) {
        const float inv = 1.0f / (sqrtf(tot) + EPS);
        if (tid < 192) {
            dst[2 * tid]     = h2(f.x * inv, f.y * inv);
            dst[2 * tid + 1] = h2(f.z * inv, f.w * inv);
        }
    } else {
        if (tid < 192) {
            dst[2 * tid]     = h2(f.x, f.y);
            dst[2 * tid + 1] = h2(f.z, f.w);
        }
        if (tid == 0) magdst[0] = sqrtf(tot) * (1.0f / sqrtf((float)D));
    }
}

// ---------------------------------------------------------------------------
// fp16 GEMM core (R3-proven skeleton): C[128 x 64] = A[m0..][:] * W[n0..][:]^T
// 8 warps (4m x 2n), warp tile 32x32. Register-prefetch single smem buffer.
// Operands are half2-packed uint32; row = Dh uint32.
// ---------------------------------------------------------------------------
__device__ __forceinline__ void gemm_core(const uint32_t* __restrict__ A,
                                          const uint32_t* __restrict__ W,
                                          int m0, int n0,
                                          uint32_t* As, uint32_t* Bs,
                                          float (&acc)[2][4][4], int tid) {
    const int lane = tid & 31, warp = tid >> 5;
    const int wm = warp >> 1, wn = warp & 1;
    const int g = lane >> 2, c = lane & 3;
    const uint32_t* Ab = A + (size_t)m0 * Dh;
    const uint32_t* Wb = W + (size_t)n0 * Dh;
    const int ar = tid >> 2, ac = (tid & 3) * 4;   // staging: row, uint32-col*4

    uint4 pa0 = *(const uint4*)&Ab[(size_t)ar * Dh + ac];
    uint4 pa1 = *(const uint4*)&Ab[(size_t)(ar + 64) * Dh + ac];
    uint4 pb  = *(const uint4*)&Wb[(size_t)ar * Dh + ac];

    for (int k = 0; k < NC; k++) {
        if (k) __syncthreads();
        *(uint4*)&As[ar * PAD + ac]        = pa0;
        *(uint4*)&As[(ar + 64) * PAD + ac] = pa1;
        *(uint4*)&Bs[ar * PAD + ac]        = pb;
        __syncthreads();
        if (k + 1 < NC) {
            const int k0 = (k + 1) * KC;
            pa0 = *(const uint4*)&Ab[(size_t)ar * Dh + k0 + ac];
            pa1 = *(const uint4*)&Ab[(size_t)(ar + 64) * Dh + k0 + ac];
            pb  = *(const uint4*)&Wb[(size_t)ar * Dh + k0 + ac];
        }
#pragma unroll
        for (int ks = 0; ks < 2; ks++) {
            const int kk = ks * 8;
            uint32_t af[2][4], bf[4][2];
#pragma unroll
            for (int mt = 0; mt < 2; mt++) {
                const uint32_t* p = &As[(wm * 32 + mt * 16 + g) * PAD + kk + c];
                af[mt][0] = p[0];        af[mt][2] = p[4];
                af[mt][1] = p[8 * PAD];  af[mt][3] = p[8 * PAD + 4];
            }
#pragma unroll
            for (int nt = 0; nt < 4; nt++) {
                const uint32_t* p = &Bs[(wn * 32 + nt * 8 + g) * PAD + kk + c];
                bf[nt][0] = p[0]; bf[nt][1] = p[4];
            }
#pragma unroll
            for (int mt = 0; mt < 2; mt++)
#pragma unroll
                for (int nt = 0; nt < 4; nt++) mma16(acc[mt][nt], af[mt], bf[nt]);
        }
    }
}

// ---------------------------------------------------------------------------
// Kernel 2: qkv GEMM + per-head q/k RMS-normalize + scatter.
// Block tile n-extent 64 == one head. Q/K stored half2-packed; V stored
// TRANSPOSED in global ([b][h][d][t], half) for the PV mma B-operand.
// grid: (2304/64, 8192/128)
// ---------------------------------------------------------------------------
__global__ void __launch_bounds__(256) qkv_mm() {
    __shared__ __align__(16) uint32_t As[128 * PAD];
    __shared__ __align__(16) uint32_t Bs[64 * PAD];
    __shared__ float part[2][128];
    const int n0 = blockIdx.x * 64, m0 = blockIdx.y * 128;
    const int tid = threadIdx.x, lane = tid & 31, warp = tid >> 5;
    const int wm = warp >> 1, wn = warp & 1, g = lane >> 2, c = lane & 3;

    float acc[2][4][4] = {};
    gemm_core(g_xh, g_wq, m0, n0, As, Bs, acc, tid);

    const int which = n0 / D;                 // 0=q 1=k 2=v
    const int h = (n0 % D) / HD;
    const int b = m0 / T;

    if (which < 2) {
#pragma unroll
        for (int mt = 0; mt < 2; mt++) {
            float s0 = 0.f, s1 = 0.f;
#pragma unroll
            for (int nt = 0; nt < 4; nt++) {
                s0 += acc[mt][nt][0] * acc[mt][nt][0] + acc[mt][nt][1] * acc[mt][nt][1];
                s1 += acc[mt][nt][2] * acc[mt][nt][2] + acc[mt][nt][3] * acc[mt][nt][3];
            }
            s0 += __shfl_xor_sync(~0u, s0, 1); s0 += __shfl_xor_sync(~0u, s0, 2);
            s1 += __shfl_xor_sync(~0u, s1, 1); s1 += __shfl_xor_sync(~0u, s1, 2);
            if (c == 0) {
                part[wn][wm * 32 + mt * 16 + g]     = s0;
                part[wn][wm * 32 + mt * 16 + g + 8] = s1;
            }
        }
        __syncthreads();
        uint32_t* dstb = (which == 0) ? g_Q : g_K;
#pragma unroll
        for (int mt = 0; mt < 2; mt++) {
#pragma unroll
            for (int rr = 0; rr < 2; rr++) {
                const int ml = wm * 32 + mt * 16 + g + rr * 8;
                const int t = (m0 + ml) & (T - 1);
                const float ss = part[0][ml] + part[1][ml];
                const float sc = 8.0f / (sqrtf(ss) + EPS);   // sqrt(HD)=8
                uint32_t* dp = dstb + (((size_t)(b * H + h)) * T + t) * (HD / 2);
#pragma unroll
                for (int nt = 0; nt < 4; nt++)
                    dp[wn * 16 + nt * 4 + c] = h2(acc[mt][nt][rr * 2] * sc,
                                                  acc[mt][nt][rr * 2 + 1] * sc);
            }
        }
    } else {
        // V: store transposed [d][t] halves
        __half* vb = g_Vt + ((size_t)(b * H + h)) * HD * T;
#pragma unroll
        for (int mt = 0; mt < 2; mt++) {
#pragma unroll
            for (int rr = 0; rr < 2; rr++) {
                const int t = (m0 + wm * 32 + mt * 16 + g + rr * 8) & (T - 1);
#pragma unroll
                for (int nt = 0; nt < 4; nt++) {
                    const int d = wn * 32 + nt * 8 + 2 * c;
                    vb[(size_t)d * T + t]       = __float2half(acc[mt][nt][rr * 2]);
                    vb[(size_t)(d + 1) * T + t] = __float2half(acc[mt][nt][rr * 2 + 1]);
                }
            }
        }
    }
}

// ---------------------------------------------------------------------------
// Kernel 3: fused sigmoid attention, fp16 mma k16.
// Block: 128 q-rows, 8 warps (16 rows x 64 cols). Q frags in registers.
// P (S C-frags) -> PV A-frags by pure in-thread f16x2 packing (no shuffles).
// grid: (T/128, H, B). 18KB static smem.
// ---------------------------------------------------------------------------
__global__ void __launch_bounds__(256) attn_mma() {
    __shared__ __align__(16) uint32_t Ks[64 * APAD];   // [key][d-pairs]
    __shared__ __align__(16) uint32_t Vs[64 * APAD];   // [d][key-pairs]
    const int tid = threadIdx.x, lane = tid & 31, warp = tid >> 5;
    const int g = lane >> 2, c = lane & 3;
    const int q0 = blockIdx.x * 128;
    const int h = blockIdx.y, b = blockIdx.z;
    const size_t bh = ((size_t)(b * H + h)) * T;

    // Q fragments (16 rows x 64 k = 4 k-steps), persistent in registers
    uint32_t qf[4][4];
    {
        const uint32_t* Qg = g_Q + (bh + q0 + warp * 16) * (HD / 2);
#pragma unroll
        for (int ks = 0; ks < 4; ks++) {
            qf[ks][0] = Qg[(size_t)g * 32 + ks * 8 + c];
            qf[ks][1] = Qg[(size_t)(g + 8) * 32 + ks * 8 + c];
            qf[ks][2] = Qg[(size_t)g * 32 + ks * 8 + c + 4];
            qf[ks][3] = Qg[(size_t)(g + 8) * 32 + ks * 8 + c + 4];
        }
    }

    const uint32_t* Kg0  = g_K + bh * (HD / 2);
    const uint32_t* Vtg0 = (const uint32_t*)(g_Vt + bh * HD);  // rows of T/2 uint32

    float oacc[8][4] = {};

    for (int s0 = 0; s0 < T; s0 += 64) {
        __syncthreads();
        // Stage K tile [64 keys x 32 u32] and Vt tile [64 d x 32 u32], conflict-free
        {
            const uint32_t* Kg = Kg0 + (size_t)s0 * (HD / 2);
            const int sc0 = s0 >> 1;
#pragma unroll
            for (int i = 0; i < 8; i++) {
                const int l = tid + i * 256, r = l >> 5, cc = l & 31;
                Ks[r * APAD + cc] = Kg[(size_t)r * 32 + cc];
                Vs[r * APAD + cc] = Vtg0[(size_t)r * (T / 2) + sc0 + cc];
            }
        }
        __syncthreads();

        // S = Q K^T  (16 x 64 per warp), 4 ks x 8 nt
        float sacc[8][4] = {};
#pragma unroll
        for (int ks = 0; ks < 4; ks++) {
            uint32_t bf[8][2];
#pragma unroll
            for (int nt = 0; nt < 8; nt++) {
                const uint32_t* p = &Ks[(nt * 8 + g) * APAD + ks * 8 + c];
                bf[nt][0] = p[0]; bf[nt][1] = p[4];
            }
#pragma unroll
            for (int nt = 0; nt < 8; nt++) mma16(sacc[nt], qf[ks], bf[nt]);
        }

        // sigmoid(S/8)
#pragma unroll
        for (int nt = 0; nt < 8; nt++)
#pragma unroll
            for (int j = 0; j < 4; j++)
                sacc[nt][j] = fast_sigmoid8(sacc[nt][j]);

        // O += P V : A-frags are pure register packs of the S C-frags
#pragma unroll
        for (int kt = 0; kt < 4; kt++) {
            uint32_t af[4];
            af[0] = h2(sacc[2 * kt][0],     sacc[2 * kt][1]);
            af[1] = h2(sacc[2 * kt][2],     sacc[2 * kt][3]);
            af[2] = h2(sacc[2 * kt + 1][0], sacc[2 * kt + 1][1]);
            af[3] = h2(sacc[2 * kt + 1][2], sacc[2 * kt + 1][3]);
#pragma unroll
            for (int nt = 0; nt < 8; nt++) {
                uint32_t bf[2];
                const uint32_t* p = &Vs[(nt * 8 + g) * APAD + kt * 8 + c];
                bf[0] = p[0]; bf[1] = p[4];
                mma16(oacc[nt], af, bf);
            }
        }
    }

    // Epilogue: out = mag * 8*cst*acc / (cst*||acc|| + eps), half2-packed
    const float cst = GAIN * rsqrtf((float)T);
#pragma unroll
    for (int rr = 0; rr < 2; rr++) {
        float s = 0.f;
#pragma unroll
        for (int nt = 0; nt < 8; nt++)
            s += oacc[nt][rr * 2] * oacc[nt][rr * 2] + oacc[nt][rr * 2 + 1] * oacc[nt][rr * 2 + 1];
        s += __shfl_xor_sync(~0u, s, 1);
        s += __shfl_xor_sync(~0u, s, 2);
        const int t = q0 + warp * 16 + g + rr * 8;
        const float n = cst * sqrtf(s);
        const float f = 8.0f * cst * g_mag[b * T + t] / (n + EPS);
        uint32_t* dp = g_att + ((size_t)b * T + t) * Dh + h * (HD / 2);
#pragma unroll
        for (int nt = 0; nt < 8; nt++)
            dp[nt * 4 + c] = h2(oacc[nt][rr * 2] * f, oacc[nt][rr * 2 + 1] * f);
    }
}

// ---------------------------------------------------------------------------
// Kernel 4: out-projection  y = att @ wn_out^T  (fp32 out)
// grid: (768/64, 8192/128)
// ---------------------------------------------------------------------------
__global__ void __launch_bounds__(256) proj_mm(float* __restrict__ out) {
    __shared__ __align__(16) uint32_t As[128 * PAD];
    __shared__ __align__(16) uint32_t Bs[64 * PAD];
    const int n0 = blockIdx.x * 64, m0 = blockIdx.y * 128;
    const int tid = threadIdx.x, lane = tid & 31, warp = tid >> 5;
    const int wm = warp >> 1, wn = warp & 1, g = lane >> 2, c = lane & 3;

    float acc[2][4][4] = {};
    gemm_core(g_att, g_wo, m0, n0, As, Bs, acc, tid);

#pragma unroll
    for (int mt = 0; mt < 2; mt++) {
#pragma unroll
        for (int rr = 0; rr < 2; rr++) {
            const int m = m0 + wm * 32 + mt * 16 + g + rr * 8;
            float* dp = out + (size_t)m * D + n0;
#pragma unroll
            for (int nt = 0; nt < 4; nt++) {
                const int col = wn * 32 + nt * 8 + 2 * c;
                *(float2*)&dp[col] = make_float2(acc[mt][nt][rr * 2],
                                                 acc[mt][nt][rr * 2 + 1]);
            }
        }
    }
}

// ---------------------------------------------------------------------------
extern "C" void kernel_launch(void* const* d_in, const int* in_sizes, int n_in,
                              void* d_out, int out_size) {
    const float* x     = (const float*)d_in[0];
    const float* qkv_w = (const float*)d_in[1];
    const float* out_w = (const float*)d_in[2];

    prep_kernel<<<NQKV + D + BT, 256>>>(x, qkv_w, out_w);
    qkv_mm<<<dim3(NQKV / 64, BT / 128), 256>>>();
    attn_mma<<<dim3(T / 128, H, B), 256>>>();
    proj_mm<<<dim3(D / 64, BT / 128), 256>>>((float*)d_out);
}

// round 7
// speedup vs baseline: 2.8766x; 1.1023x over previous
#include <cuda_runtime.h>
#include <cuda_fp16.h>
#include <math.h>
#include <stdint.h>

// Problem constants
constexpr int B  = 4;
constexpr int T  = 2048;
constexpr int D  = 768;
constexpr int H  = 12;
constexpr int HD = 64;
constexpr int BT = B * T;          // 8192
constexpr int NQKV = 3 * D;        // 2304
constexpr float EPS  = 1e-4f;
constexpr float GAIN = 1.8402f;

constexpr int Dh   = D / 2;        // 384 uint32 (half2) per row
constexpr int PAD  = 20;           // gemm chunk row stride (16 data + 4 pad u32)
constexpr int APAD = 36;           // attn row stride (32 data + 4 pad u32)
constexpr int KC   = 16;           // gemm k-chunk in uint32 (= 32 halfs)
constexpr int NC   = Dh / KC;      // 24 chunks

// Scratch (__device__ globals; fp16 storage packed as uint32 = half2)
__device__ uint32_t g_xh[BT * Dh];
__device__ uint32_t g_wq[NQKV * Dh];
__device__ uint32_t g_wo[D * Dh];
__device__ uint32_t g_Q[B * H * T * (HD / 2)];
__device__ uint32_t g_K[B * H * T * (HD / 2)];
__device__ __half   g_Vt[(size_t)B * H * HD * T];   // V transposed: [b][h][d][t]
__device__ uint32_t g_att[BT * Dh];
__device__ float    g_mag[BT];

__device__ __forceinline__ uint32_t h2(float lo, float hi) {
    uint32_t u;  // first asm source -> upper 16 bits
    asm("cvt.rn.f16x2.f32 %0, %1, %2;" : "=r"(u) : "f"(hi), "f"(lo));
    return u;
}
__device__ __forceinline__ float fast_sigmoid8(float s) {
    float t; asm("tanh.approx.f32 %0, %1;" : "=f"(t) : "f"(s * 0.0625f));
    return fmaf(0.5f, t, 0.5f);
}
__device__ __forceinline__ void mma16(float c[4], const uint32_t a[4], const uint32_t b[2]) {
    asm volatile(
        "mma.sync.aligned.m16n8k16.row.col.f32.f16.f16.f32 "
        "{%0,%1,%2,%3}, {%4,%5,%6,%7}, {%8,%9}, {%0,%1,%2,%3};"
        : "+f"(c[0]), "+f"(c[1]), "+f"(c[2]), "+f"(c[3])
        : "r"(a[0]), "r"(a[1]), "r"(a[2]), "r"(a[3]), "r"(b[0]), "r"(b[1]));
}
__device__ __forceinline__ uint32_t saddr(const void* p) {
    return (uint32_t)__cvta_generic_to_shared(p);
}
__device__ __forceinline__ void ldsm4(uint32_t* r, uint32_t a) {
    asm volatile("ldmatrix.sync.aligned.m8n8.x4.shared.b16 {%0,%1,%2,%3}, [%4];"
                 : "=r"(r[0]), "=r"(r[1]), "=r"(r[2]), "=r"(r[3]) : "r"(a));
}

// ---------------------------------------------------------------------------
// Kernel 1: weight row-norm -> fp16; x -> fp16 copy + per-token magnitude.
// ---------------------------------------------------------------------------
__global__ void __launch_bounds__(256) prep_kernel(const float* __restrict__ x,
                                                   const float* __restrict__ qkv_w,
                                                   const float* __restrict__ out_w) {
    const int r = blockIdx.x;
    const float* src;
    uint32_t* dst;
    float* magdst = nullptr;
    bool donorm = true;
    if (r < NQKV) {
        src = qkv_w + (size_t)r * D;  dst = g_wq + (size_t)r * Dh;
    } else if (r < NQKV + D) {
        src = out_w + (size_t)(r - NQKV) * D;  dst = g_wo + (size_t)(r - NQKV) * Dh;
    } else {
        const int tr = r - (NQKV + D);
        src = x + (size_t)tr * D;  dst = g_xh + (size_t)tr * Dh;
        magdst = g_mag + tr;  donorm = false;
    }
    const int tid = threadIdx.x;
    float4 f = make_float4(0.f, 0.f, 0.f, 0.f);
    if (tid < 192) f = ((const float4*)src)[tid];
    float s = f.x * f.x + f.y * f.y + f.z * f.z + f.w * f.w;
#pragma unroll
    for (int o = 16; o > 0; o >>= 1) s += __shfl_xor_sync(0xffffffffu, s, o);
    __shared__ float red[8];
    __shared__ float stot;
    if ((tid & 31) == 0) red[tid >> 5] = s;
    __syncthreads();
    if (tid == 0) {
        float t = red[0];
#pragma unroll
        for (int i = 1; i < 8; i++) t += red[i];
        stot = t;
    }
    __syncthreads();
    const float tot = stot;
    if (donorm) {
        const float inv = 1.0f / (sqrtf(tot) + EPS);
        if (tid < 192) {
            dst[2 * tid]     = h2(f.x * inv, f.y * inv);
            dst[2 * tid + 1] = h2(f.z * inv, f.w * inv);
        }
    } else {
        if (tid < 192) {
            dst[2 * tid]     = h2(f.x, f.y);
            dst[2 * tid + 1] = h2(f.z, f.w);
        }
        if (tid == 0) magdst[0] = sqrtf(tot) * (1.0f / sqrtf((float)D));
    }
}

// ---------------------------------------------------------------------------
// fp16 GEMM core with ldmatrix fragment loads.
// C[128 x 64] = A[m0..][:] * W[n0..][:]^T, 8 warps (4m x 2n), warp tile 32x32.
// ---------------------------------------------------------------------------
__device__ __forceinline__ void gemm_core(const uint32_t* __restrict__ A,
                                          const uint32_t* __restrict__ W,
                                          int m0, int n0,
                                          uint32_t* As, uint32_t* Bs,
                                          float (&acc)[2][4][4], int tid) {
    const int lane = tid & 31, warp = tid >> 5;
    const int wm = warp >> 1, wn = warp & 1;
    const uint32_t* Ab = A + (size_t)m0 * Dh;
    const uint32_t* Wb = W + (size_t)n0 * Dh;
    const int ar = tid >> 2, ac = (tid & 3) * 4;   // staging: row, uint32-col*4

    // ldmatrix lane->address precompute
    // A x4: tiles {r0-7/kk, r8-15/kk, r0-7/kk+4, r8-15/kk+4}
    const uint32_t a_base = saddr(As) +
        (((wm * 32 + (lane & 15)) * PAD + (lane >> 4) * 4) << 2);
    // B x4 over nt-pair: tiles {n0-7/kk, n0-7/kk+4, n8-15/kk, n8-15/kk+4}
    const uint32_t b_base = saddr(Bs) +
        (((wn * 32 + ((lane >> 4) & 1) * 8 + (lane & 7)) * PAD + ((lane >> 3) & 1) * 4) << 2);

    uint4 pa0 = *(const uint4*)&Ab[(size_t)ar * Dh + ac];
    uint4 pa1 = *(const uint4*)&Ab[(size_t)(ar + 64) * Dh + ac];
    uint4 pb  = *(const uint4*)&Wb[(size_t)ar * Dh + ac];

    for (int k = 0; k < NC; k++) {
        if (k) __syncthreads();
        *(uint4*)&As[ar * PAD + ac]        = pa0;
        *(uint4*)&As[(ar + 64) * PAD + ac] = pa1;
        *(uint4*)&Bs[ar * PAD + ac]        = pb;
        __syncthreads();
        if (k + 1 < NC) {
            const int k0 = (k + 1) * KC;
            pa0 = *(const uint4*)&Ab[(size_t)ar * Dh + k0 + ac];
            pa1 = *(const uint4*)&Ab[(size_t)(ar + 64) * Dh + k0 + ac];
            pb  = *(const uint4*)&Wb[(size_t)ar * Dh + k0 + ac];
        }
#pragma unroll
        for (int ks = 0; ks < 2; ks++) {
            const int kk = ks * 8;
            uint32_t af[2][4], b0[4], b1[4];
            ldsm4(af[0], a_base + (kk << 2));
            ldsm4(af[1], a_base + ((16 * PAD + kk) << 2));
            ldsm4(b0, b_base + (kk << 2));                  // nt0, nt1
            ldsm4(b1, b_base + ((16 * PAD + kk) << 2));     // nt2, nt3
#pragma unroll
            for (int mt = 0; mt < 2; mt++) {
                mma16(acc[mt][0], af[mt], b0);
                mma16(acc[mt][1], af[mt], b0 + 2);
                mma16(acc[mt][2], af[mt], b1);
                mma16(acc[mt][3], af[mt], b1 + 2);
            }
        }
    }
}

// ---------------------------------------------------------------------------
// Kernel 2: qkv GEMM + per-head q/k RMS-normalize + scatter.
// grid: (2304/64, 8192/128)
// ---------------------------------------------------------------------------
__global__ void __launch_bounds__(256) qkv_mm() {
    __shared__ __align__(16) uint32_t As[128 * PAD];
    __shared__ __align__(16) uint32_t Bs[64 * PAD];
    __shared__ float part[2][128];
    const int n0 = blockIdx.x * 64, m0 = blockIdx.y * 128;
    const int tid = threadIdx.x, lane = tid & 31, warp = tid >> 5;
    const int wm = warp >> 1, wn = warp & 1, g = lane >> 2, c = lane & 3;

    float acc[2][4][4] = {};
    gemm_core(g_xh, g_wq, m0, n0, As, Bs, acc, tid);

    const int which = n0 / D;                 // 0=q 1=k 2=v
    const int h = (n0 % D) / HD;
    const int b = m0 / T;

    if (which < 2) {
#pragma unroll
        for (int mt = 0; mt < 2; mt++) {
            float s0 = 0.f, s1 = 0.f;
#pragma unroll
            for (int nt = 0; nt < 4; nt++) {
                s0 += acc[mt][nt][0] * acc[mt][nt][0] + acc[mt][nt][1] * acc[mt][nt][1];
                s1 += acc[mt][nt][2] * acc[mt][nt][2] + acc[mt][nt][3] * acc[mt][nt][3];
            }
            s0 += __shfl_xor_sync(~0u, s0, 1); s0 += __shfl_xor_sync(~0u, s0, 2);
            s1 += __shfl_xor_sync(~0u, s1, 1); s1 += __shfl_xor_sync(~0u, s1, 2);
            if (c == 0) {
                part[wn][wm * 32 + mt * 16 + g]     = s0;
                part[wn][wm * 32 + mt * 16 + g + 8] = s1;
            }
        }
        __syncthreads();
        uint32_t* dstb = (which == 0) ? g_Q : g_K;
#pragma unroll
        for (int mt = 0; mt < 2; mt++) {
#pragma unroll
            for (int rr = 0; rr < 2; rr++) {
                const int ml = wm * 32 + mt * 16 + g + rr * 8;
                const int t = (m0 + ml) & (T - 1);
                const float ss = part[0][ml] + part[1][ml];
                const float sc = 8.0f / (sqrtf(ss) + EPS);   // sqrt(HD)=8
                uint32_t* dp = dstb + (((size_t)(b * H + h)) * T + t) * (HD / 2);
#pragma unroll
                for (int nt = 0; nt < 4; nt++)
                    dp[wn * 16 + nt * 4 + c] = h2(acc[mt][nt][rr * 2] * sc,
                                                  acc[mt][nt][rr * 2 + 1] * sc);
            }
        }
    } else {
        // V: store transposed [d][t] halves
        __half* vb = g_Vt + ((size_t)(b * H + h)) * HD * T;
#pragma unroll
        for (int mt = 0; mt < 2; mt++) {
#pragma unroll
            for (int rr = 0; rr < 2; rr++) {
                const int t = (m0 + wm * 32 + mt * 16 + g + rr * 8) & (T - 1);
#pragma unroll
                for (int nt = 0; nt < 4; nt++) {
                    const int d = wn * 32 + nt * 8 + 2 * c;
                    vb[(size_t)d * T + t]       = __float2half(acc[mt][nt][rr * 2]);
                    vb[(size_t)(d + 1) * T + t] = __float2half(acc[mt][nt][rr * 2 + 1]);
                }
            }
        }
    }
}

// ---------------------------------------------------------------------------
// Kernel 3: fused sigmoid attention, fp16 mma k16 + ldmatrix.
// Block: 128 q-rows, 8 warps (16 rows x 64 cols). Q frags in registers.
// grid: (T/128, H, B). 18KB static smem.
// ---------------------------------------------------------------------------
__global__ void __launch_bounds__(256) attn_mma() {
    __shared__ __align__(16) uint32_t Ks[64 * APAD];   // [key][d-pairs]
    __shared__ __align__(16) uint32_t Vs[64 * APAD];   // [d][key-pairs]
    const int tid = threadIdx.x, lane = tid & 31, warp = tid >> 5;
    const int g = lane >> 2, c = lane & 3;
    const int q0 = blockIdx.x * 128;
    const int h = blockIdx.y, b = blockIdx.z;
    const size_t bh = ((size_t)(b * H + h)) * T;

    // Q fragments (16 rows x 64 k = 4 k-steps), persistent in registers
    uint32_t qf[4][4];
    {
        const uint32_t* Qg = g_Q + (bh + q0 + warp * 16) * (HD / 2);
#pragma unroll
        for (int ks = 0; ks < 4; ks++) {
            qf[ks][0] = Qg[(size_t)g * 32 + ks * 8 + c];
            qf[ks][1] = Qg[(size_t)(g + 8) * 32 + ks * 8 + c];
            qf[ks][2] = Qg[(size_t)g * 32 + ks * 8 + c + 4];
            qf[ks][3] = Qg[(size_t)(g + 8) * 32 + ks * 8 + c + 4];
        }
    }

    // ldmatrix B-frag base addresses (nt-pair x4 tiles) for Ks and Vs
    const uint32_t krow = ((lane >> 4) & 1) * 8 + (lane & 7);
    const uint32_t kcol = ((lane >> 3) & 1) * 4;
    const uint32_t kb = saddr(Ks) + ((krow * APAD + kcol) << 2);
    const uint32_t vb = saddr(Vs) + ((krow * APAD + kcol) << 2);

    const uint32_t* Kg0  = g_K + bh * (HD / 2);
    const uint32_t* Vtg0 = (const uint32_t*)(g_Vt + bh * HD);  // rows of T/2 uint32

    float oacc[8][4] = {};

    for (int s0 = 0; s0 < T; s0 += 64) {
        __syncthreads();
        {
            const uint32_t* Kg = Kg0 + (size_t)s0 * (HD / 2);
            const int sc0 = s0 >> 1;
#pragma unroll
            for (int i = 0; i < 8; i++) {
                const int l = tid + i * 256, r = l >> 5, cc = l & 31;
                Ks[r * APAD + cc] = Kg[(size_t)r * 32 + cc];
                Vs[r * APAD + cc] = Vtg0[(size_t)r * (T / 2) + sc0 + cc];
            }
        }
        __syncthreads();

        // S = Q K^T  (16 x 64 per warp), 4 ks x 8 nt
        float sacc[8][4] = {};
#pragma unroll
        for (int ks = 0; ks < 4; ks++) {
            uint32_t bq[4][4];
#pragma unroll
            for (int np = 0; np < 4; np++)
                ldsm4(bq[np], kb + ((np * 16 * APAD + ks * 8) << 2));
#pragma unroll
            for (int np = 0; np < 4; np++) {
                mma16(sacc[2 * np],     qf[ks], bq[np]);
                mma16(sacc[2 * np + 1], qf[ks], bq[np] + 2);
            }
        }

        // sigmoid(S/8)
#pragma unroll
        for (int nt = 0; nt < 8; nt++)
#pragma unroll
            for (int j = 0; j < 4; j++)
                sacc[nt][j] = fast_sigmoid8(sacc[nt][j]);

        // O += P V : A-frags are pure register packs of the S C-frags
#pragma unroll
        for (int kt = 0; kt < 4; kt++) {
            uint32_t af[4];
            af[0] = h2(sacc[2 * kt][0],     sacc[2 * kt][1]);
            af[1] = h2(sacc[2 * kt][2],     sacc[2 * kt][3]);
            af[2] = h2(sacc[2 * kt + 1][0], sacc[2 * kt + 1][1]);
            af[3] = h2(sacc[2 * kt + 1][2], sacc[2 * kt + 1][3]);
            uint32_t bq[4][4];
#pragma unroll
            for (int np = 0; np < 4; np++)
                ldsm4(bq[np], vb + ((np * 16 * APAD + kt * 8) << 2));
#pragma unroll
            for (int np = 0; np < 4; np++) {
                mma16(oacc[2 * np],     af, bq[np]);
                mma16(oacc[2 * np + 1], af, bq[np] + 2);
            }
        }
    }

    // Epilogue: out = mag * 8*cst*acc / (cst*||acc|| + eps), half2-packed
    const float cst = GAIN * rsqrtf((float)T);
#pragma unroll
    for (int rr = 0; rr < 2; rr++) {
        float s = 0.f;
#pragma unroll
        for (int nt = 0; nt < 8; nt++)
            s += oacc[nt][rr * 2] * oacc[nt][rr * 2] + oacc[nt][rr * 2 + 1] * oacc[nt][rr * 2 + 1];
        s += __shfl_xor_sync(~0u, s, 1);
        s += __shfl_xor_sync(~0u, s, 2);
        const int t = q0 + warp * 16 + g + rr * 8;
        const float n = cst * sqrtf(s);
        const float f = 8.0f * cst * g_mag[b * T + t] / (n + EPS);
        uint32_t* dp = g_att + ((size_t)b * T + t) * Dh + h * (HD / 2);
#pragma unroll
        for (int nt = 0; nt < 8; nt++)
            dp[nt * 4 + c] = h2(oacc[nt][rr * 2] * f, oacc[nt][rr * 2 + 1] * f);
    }
}

// ---------------------------------------------------------------------------
// Kernel 4: out-projection  y = att @ wn_out^T  (fp32 out)
// grid: (768/64, 8192/128)
// ---------------------------------------------------------------------------
__global__ void __launch_bounds__(256) proj_mm(float* __restrict__ out) {
    __shared__ __align__(16) uint32_t As[128 * PAD];
    __shared__ __align__(16) uint32_t Bs[64 * PAD];
    const int n0 = blockIdx.x * 64, m0 = blockIdx.y * 128;
    const int tid = threadIdx.x, lane = tid & 31, warp = tid >> 5;
    const int wm = warp >> 1, wn = warp & 1, g = lane >> 2, c = lane & 3;

    float acc[2][4][4] = {};
    gemm_core(g_att, g_wo, m0, n0, As, Bs, acc, tid);

#pragma unroll
    for (int mt = 0; mt < 2; mt++) {
#pragma unroll
        for (int rr = 0; rr < 2; rr++) {
            const int m = m0 + wm * 32 + mt * 16 + g + rr * 8;
            float* dp = out + (size_t)m * D + n0;
#pragma unroll
            for (int nt = 0; nt < 4; nt++) {
                const int col = wn * 32 + nt * 8 + 2 * c;
                *(float2*)&dp[col] = make_float2(acc[mt][nt][rr * 2],
                                                 acc[mt][nt][rr * 2 + 1]);
            }
        }
    }
}

// ---------------------------------------------------------------------------
extern "C" void kernel_launch(void* const* d_in, const int* in_sizes, int n_in,
                              void* d_out, int out_size) {
    const float* x     = (const float*)d_in[0];
    const float* qkv_w = (const float*)d_in[1];
    const float* out_w = (const float*)d_in[2];

    prep_kernel<<<NQKV + D + BT, 256>>>(x, qkv_w, out_w);
    qkv_mm<<<dim3(NQKV / 64, BT / 128), 256>>>();
    attn_mma<<<dim3(T / 128, H, B), 256>>>();
    proj_mm<<<dim3(D / 64, BT / 128), 256>>>((float*)d_out);
}

// round 9
// speedup vs baseline: 3.6440x; 1.2668x over previous
#include <cuda_runtime.h>
#include <cuda_fp16.h>
#include <math.h>
#include <stdint.h>

// Problem constants
constexpr int B  = 4;
constexpr int T  = 2048;
constexpr int D  = 768;
constexpr int H  = 12;
constexpr int HD = 64;
constexpr int BT = B * T;          // 8192
constexpr int NQKV = 3 * D;        // 2304
constexpr float EPS  = 1e-4f;
constexpr float GAIN = 1.8402f;

constexpr int Dh   = D / 2;        // 384 uint32 (half2) per row
constexpr int PAD  = 20;           // gemm chunk row stride (16 data + 4 pad u32)
constexpr int APAD = 36;           // attn row stride (32 data + 4 pad u32)
constexpr int KC   = 16;           // gemm k-chunk in uint32 (= 32 halfs)
constexpr int NC   = Dh / KC;      // 24 chunks
constexpr int NCT  = T / 64;       // 32 attention KV chunks

// GEMM 3-stage smem layout (u32 units)
constexpr int A_U32   = 128 * PAD;           // 2560
constexpr int B_U32   = 64 * PAD;            // 1280
constexpr int STG_U32 = A_U32 + B_U32;       // 3840 (15360 B)
constexpr int GEMM_SMEM = 3 * STG_U32 * 4;   // 46080 B
// Attn 3-stage smem layout
constexpr int AK_U32   = 64 * APAD;          // 2304
constexpr int ASTG_U32 = 2 * AK_U32;         // K+V = 4608 (18432 B)
constexpr int ATTN_SMEM = 3 * ASTG_U32 * 4;  // 55296 B

// Scratch (__device__ globals; fp16 storage packed as uint32 = half2)
__device__ uint32_t g_xh[BT * Dh];
__device__ uint32_t g_wq[NQKV * Dh];
__device__ uint32_t g_wo[D * Dh];
__device__ uint32_t g_Q[B * H * T * (HD / 2)];
__device__ uint32_t g_K[B * H * T * (HD / 2)];
__device__ __half   g_Vt[(size_t)B * H * HD * T];   // V transposed: [b][h][d][t]
__device__ uint32_t g_att[BT * Dh];
__device__ float    g_mag[BT];

__device__ __forceinline__ uint32_t h2(float lo, float hi) {
    uint32_t u;  // first asm source -> upper 16 bits
    asm("cvt.rn.f16x2.f32 %0, %1, %2;" : "=r"(u) : "f"(hi), "f"(lo));
    return u;
}
__device__ __forceinline__ float fast_sigmoid8(float s) {
    float t; asm("tanh.approx.f32 %0, %1;" : "=f"(t) : "f"(s * 0.0625f));
    return fmaf(0.5f, t, 0.5f);
}
__device__ __forceinline__ void mma16(float c[4], const uint32_t a[4], const uint32_t b[2]) {
    asm volatile(
        "mma.sync.aligned.m16n8k16.row.col.f32.f16.f16.f32 "
        "{%0,%1,%2,%3}, {%4,%5,%6,%7}, {%8,%9}, {%0,%1,%2,%3};"
        : "+f"(c[0]), "+f"(c[1]), "+f"(c[2]), "+f"(c[3])
        : "r"(a[0]), "r"(a[1]), "r"(a[2]), "r"(a[3]), "r"(b[0]), "r"(b[1]));
}
__device__ __forceinline__ uint32_t saddr(const void* p) {
    return (uint32_t)__cvta_generic_to_shared(p);
}
__device__ __forceinline__ void ldsm4(uint32_t* r, uint32_t a) {
    asm volatile("ldmatrix.sync.aligned.m8n8.x4.shared.b16 {%0,%1,%2,%3}, [%4];"
                 : "=r"(r[0]), "=r"(r[1]), "=r"(r[2]), "=r"(r[3]) : "r"(a));
}
__device__ __forceinline__ void cp16(uint32_t s, const void* g) {
    asm volatile("cp.async.cg.shared.global [%0], [%1], 16;" :: "r"(s), "l"(g));
}
__device__ __forceinline__ void cp_commit() {
    asm volatile("cp.async.commit_group;" ::: "memory");
}
template <int N>
__device__ __forceinline__ void cp_wait() {
    asm volatile("cp.async.wait_group %0;" :: "n"(N) : "memory");
}

// ---------------------------------------------------------------------------
// Kernel 1: weight row-norm -> fp16; x -> fp16 copy + per-token magnitude.
// ---------------------------------------------------------------------------
__global__ void __launch_bounds__(256) prep_kernel(const float* __restrict__ x,
                                                   const float* __restrict__ qkv_w,
                                                   const float* __restrict__ out_w) {
    const int r = blockIdx.x;
    const float* src;
    uint32_t* dst;
    float* magdst = nullptr;
    bool donorm = true;
    if (r < NQKV) {
        src = qkv_w + (size_t)r * D;  dst = g_wq + (size_t)r * Dh;
    } else if (r < NQKV + D) {
        src = out_w + (size_t)(r - NQKV) * D;  dst = g_wo + (size_t)(r - NQKV) * Dh;
    } else {
        const int tr = r - (NQKV + D);
        src = x + (size_t)tr * D;  dst = g_xh + (size_t)tr * Dh;
        magdst = g_mag + tr;  donorm = false;
    }
    const int tid = threadIdx.x;
    float4 f = make_float4(0.f, 0.f, 0.f, 0.f);
    if (tid < 192) f = ((const float4*)src)[tid];
    float s = f.x * f.x + f.y * f.y + f.z * f.z + f.w * f.w;
#pragma unroll
    for (int o = 16; o > 0; o >>= 1) s += __shfl_xor_sync(0xffffffffu, s, o);
    __shared__ float red[8];
    __shared__ float stot;
    if ((tid & 31) == 0) red[tid >> 5] = s;
    __syncthreads();
    if (tid == 0) {
        float t = red[0];
#pragma unroll
        for (int i = 1; i < 8; i++) t += red[i];
        stot = t;
    }
    __syncthreads();
    const float tot = stot;
    if (donorm) {
        const float inv = 1.0f / (sqrtf(tot) + EPS);
        if (tid < 192) {
            dst[2 * tid]     = h2(f.x * inv, f.y * inv);
            dst[2 * tid + 1] = h2(f.z * inv, f.w * inv);
        }
    } else {
        if (tid < 192) {
            dst[2 * tid]     = h2(f.x, f.y);
            dst[2 * tid + 1] = h2(f.z, f.w);
        }
        if (tid == 0) magdst[0] = sqrtf(tot) * (1.0f / sqrtf((float)D));
    }
}

// ---------------------------------------------------------------------------
// fp16 GEMM core: 3-stage cp.async pipeline, one __syncthreads per chunk.
// C[128 x 64] = A[m0..][:] * W[n0..][:]^T, 8 warps (4m x 2n), warp tile 32x32.
// ---------------------------------------------------------------------------
__device__ __forceinline__ void gemm_core(const uint32_t* __restrict__ A,
                                          const uint32_t* __restrict__ W,
                                          int m0, int n0, uint32_t* sm,
                                          float (&acc)[2][4][4], int tid) {
    const int lane = tid & 31, warp = tid >> 5;
    const int wm = warp >> 1, wn = warp & 1;
    const uint32_t* Ab = A + (size_t)m0 * Dh;
    const uint32_t* Wb = W + (size_t)n0 * Dh;
    const uint32_t sb = saddr(sm);

    // ldmatrix offsets relative to a stage base (bytes)
    const uint32_t a_off = ((wm * 32 + (lane & 15)) * PAD + (lane >> 4) * 4) << 2;
    const uint32_t b_off = (A_U32 + (wn * 32 + ((lane >> 4) & 1) * 8 + (lane & 7)) * PAD +
                            ((lane >> 3) & 1) * 4) << 2;

    auto stage = [&](int s, int c) {
        const uint32_t base = sb + (uint32_t)(s * STG_U32) * 4;
        const int k0 = c * KC;
#pragma unroll
        for (int j = 0; j < 2; j++) {            // A: 128 rows x 4 segs of 16B
            const int idx = tid + j * 256;
            const int row = idx >> 2, seg = idx & 3;
            cp16(base + ((row * PAD + seg * 4) << 2), Ab + (size_t)row * Dh + k0 + seg * 4);
        }
        {                                        // B: 64 rows x 4 segs
            const int row = tid >> 2, seg = tid & 3;
            cp16(base + ((A_U32 + row * PAD + seg * 4) << 2), Wb + (size_t)row * Dh + k0 + seg * 4);
        }
        cp_commit();
    };

    stage(0, 0);
    stage(1, 1);
    for (int k = 0; k < NC; k++) {
        if (k + 1 < NC) cp_wait<1>(); else cp_wait<0>();
        __syncthreads();
        const uint32_t base = sb + (uint32_t)((k % 3) * STG_U32) * 4;
#pragma unroll
        for (int ks = 0; ks < 2; ks++) {
            const uint32_t kk4 = (ks * 8) << 2;
            uint32_t af[2][4], b0[4], b1[4];
            ldsm4(af[0], base + a_off + kk4);
            ldsm4(af[1], base + a_off + ((16 * PAD) << 2) + kk4);
            ldsm4(b0, base + b_off + kk4);
            ldsm4(b1, base + b_off + ((16 * PAD) << 2) + kk4);
#pragma unroll
            for (int mt = 0; mt < 2; mt++) {
                mma16(acc[mt][0], af[mt], b0);
                mma16(acc[mt][1], af[mt], b0 + 2);
                mma16(acc[mt][2], af[mt], b1);
                mma16(acc[mt][3], af[mt], b1 + 2);
            }
        }
        if (k + 2 < NC) stage((k + 2) % 3, k + 2);
    }
}

// ---------------------------------------------------------------------------
// Kernel 2: qkv GEMM + per-head q/k RMS-normalize + scatter.
// grid: (2304/64, 8192/128)
// ---------------------------------------------------------------------------
__global__ void __launch_bounds__(256) qkv_mm() {
    extern __shared__ __align__(16) uint32_t dsm[];
    __shared__ float part[2][128];
    const int n0 = blockIdx.x * 64, m0 = blockIdx.y * 128;
    const int tid = threadIdx.x, lane = tid & 31, warp = tid >> 5;
    const int wm = warp >> 1, wn = warp & 1, g = lane >> 2, c = lane & 3;

    float acc[2][4][4] = {};
    gemm_core(g_xh, g_wq, m0, n0, dsm, acc, tid);

    const int which = n0 / D;                 // 0=q 1=k 2=v
    const int h = (n0 % D) / HD;
    const int b = m0 / T;

    if (which < 2) {
#pragma unroll
        for (int mt = 0; mt < 2; mt++) {
            float s0 = 0.f, s1 = 0.f;
#pragma unroll
            for (int nt = 0; nt < 4; nt++) {
                s0 += acc[mt][nt][0] * acc[mt][nt][0] + acc[mt][nt][1] * acc[mt][nt][1];
                s1 += acc[mt][nt][2] * acc[mt][nt][2] + acc[mt][nt][3] * acc[mt][nt][3];
            }
            s0 += __shfl_xor_sync(~0u, s0, 1); s0 += __shfl_xor_sync(~0u, s0, 2);
            s1 += __shfl_xor_sync(~0u, s1, 1); s1 += __shfl_xor_sync(~0u, s1, 2);
            if (c == 0) {
                part[wn][wm * 32 + mt * 16 + g]     = s0;
                part[wn][wm * 32 + mt * 16 + g + 8] = s1;
            }
        }
        __syncthreads();
        uint32_t* dstb = (which == 0) ? g_Q : g_K;
#pragma unroll
        for (int mt = 0; mt < 2; mt++) {
#pragma unroll
            for (int rr = 0; rr < 2; rr++) {
                const int ml = wm * 32 + mt * 16 + g + rr * 8;
                const int t = (m0 + ml) & (T - 1);
                const float ss = part[0][ml] + part[1][ml];
                const float sc = 8.0f / (sqrtf(ss) + EPS);   // sqrt(HD)=8
                uint32_t* dp = dstb + (((size_t)(b * H + h)) * T + t) * (HD / 2);
#pragma unroll
                for (int nt = 0; nt < 4; nt++)
                    dp[wn * 16 + nt * 4 + c] = h2(acc[mt][nt][rr * 2] * sc,
                                                  acc[mt][nt][rr * 2 + 1] * sc);
            }
        }
    } else {
        // V: store transposed [d][t] halves
        __half* vb = g_Vt + ((size_t)(b * H + h)) * HD * T;
#pragma unroll
        for (int mt = 0; mt < 2; mt++) {
#pragma unroll
            for (int rr = 0; rr < 2; rr++) {
                const int t = (m0 + wm * 32 + mt * 16 + g + rr * 8) & (T - 1);
#pragma unroll
                for (int nt = 0; nt < 4; nt++) {
                    const int d = wn * 32 + nt * 8 + 2 * c;
                    vb[(size_t)d * T + t]       = __float2half(acc[mt][nt][rr * 2]);
                    vb[(size_t)(d + 1) * T + t] = __float2half(acc[mt][nt][rr * 2 + 1]);
                }
            }
        }
    }
}

// ---------------------------------------------------------------------------
// Kernel 3: fused sigmoid attention, 3-stage cp.async K/V pipeline.
// Block: 128 q-rows, 8 warps (16 rows x 64 cols). Q frags in registers.
// grid: (T/128, H, B). 55296 B dynamic smem.
// ---------------------------------------------------------------------------
__global__ void __launch_bounds__(256) attn_mma() {
    extern __shared__ __align__(16) uint32_t dsm[];
    const int tid = threadIdx.x, lane = tid & 31, warp = tid >> 5;
    const int g = lane >> 2, c = lane & 3;
    const int q0 = blockIdx.x * 128;
    const int h = blockIdx.y, b = blockIdx.z;
    const size_t bh = ((size_t)(b * H + h)) * T;

    // Q fragments (16 rows x 64 k = 4 k-steps), persistent in registers
    uint32_t qf[4][4];
    {
        const uint32_t* Qg = g_Q + (bh + q0 + warp * 16) * (HD / 2);
#pragma unroll
        for (int ks = 0; ks < 4; ks++) {
            qf[ks][0] = Qg[(size_t)g * 32 + ks * 8 + c];
            qf[ks][1] = Qg[(size_t)(g + 8) * 32 + ks * 8 + c];
            qf[ks][2] = Qg[(size_t)g * 32 + ks * 8 + c + 4];
            qf[ks][3] = Qg[(size_t)(g + 8) * 32 + ks * 8 + c + 4];
        }
    }

    const uint32_t sb = saddr(dsm);
    // ldmatrix offsets relative to a stage base (bytes)
    const uint32_t krow = ((lane >> 4) & 1) * 8 + (lane & 7);
    const uint32_t kcol = ((lane >> 3) & 1) * 4;
    const uint32_t kb_off = (krow * APAD + kcol) << 2;
    const uint32_t vb_off = ((AK_U32 + krow * APAD + kcol)) << 2;

    const uint32_t* Kg0  = g_K + bh * (HD / 2);
    const uint32_t* Vtg0 = (const uint32_t*)(g_Vt + bh * HD);  // rows of T/2 uint32

    auto stage_kv = [&](int s, int i) {
        const uint32_t base = sb + (uint32_t)(s * ASTG_U32) * 4;
        const int s0 = i * 64, sc0 = s0 >> 1;
#pragma unroll
        for (int j = 0; j < 2; j++) {
            const int idx = tid + j * 256;
            const int row = idx >> 3, seg = idx & 7;
            cp16(base + ((row * APAD + seg * 4) << 2),
                 Kg0 + (size_t)(s0 + row) * 32 + seg * 4);
            cp16(base + ((AK_U32 + row * APAD + seg * 4) << 2),
                 Vtg0 + (size_t)row * (T / 2) + sc0 + seg * 4);
        }
        cp_commit();
    };

    float oacc[8][4] = {};

    stage_kv(0, 0);
    stage_kv(1, 1);
    for (int i = 0; i < NCT; i++) {
        if (i + 1 < NCT) cp_wait<1>(); else cp_wait<0>();
        __syncthreads();
        const uint32_t base = sb + (uint32_t)((i % 3) * ASTG_U32) * 4;

        // S = Q K^T  (16 x 64 per warp), 4 ks x 8 nt
        float sacc[8][4] = {};
#pragma unroll
        for (int ks = 0; ks < 4; ks++) {
            uint32_t bq[4][4];
#pragma unroll
            for (int np = 0; np < 4; np++)
                ldsm4(bq[np], base + kb_off + ((np * 16 * APAD + ks * 8) << 2));
#pragma unroll
            for (int np = 0; np < 4; np++) {
                mma16(sacc[2 * np],     qf[ks], bq[np]);
                mma16(sacc[2 * np + 1], qf[ks], bq[np] + 2);
            }
        }

        // sigmoid(S/8)
#pragma unroll
        for (int nt = 0; nt < 8; nt++)
#pragma unroll
            for (int j = 0; j < 4; j++)
                sacc[nt][j] = fast_sigmoid8(sacc[nt][j]);

        // O += P V : A-frags are pure register packs of the S C-frags
#pragma unroll
        for (int kt = 0; kt < 4; kt++) {
            uint32_t af[4];
            af[0] = h2(sacc[2 * kt][0],     sacc[2 * kt][1]);
            af[1] = h2(sacc[2 * kt][2],     sacc[2 * kt][3]);
            af[2] = h2(sacc[2 * kt + 1][0], sacc[2 * kt + 1][1]);
            af[3] = h2(sacc[2 * kt + 1][2], sacc[2 * kt + 1][3]);
            uint32_t bq[4][4];
#pragma unroll
            for (int np = 0; np < 4; np++)
                ldsm4(bq[np], base + vb_off + ((np * 16 * APAD + kt * 8) << 2));
#pragma unroll
            for (int np = 0; np < 4; np++) {
                mma16(oacc[2 * np],     af, bq[np]);
                mma16(oacc[2 * np + 1], af, bq[np] + 2);
            }
        }
        if (i + 2 < NCT) stage_kv((i + 2) % 3, i + 2);
    }

    // Epilogue: out = mag * 8*cst*acc / (cst*||acc|| + eps), half2-packed
    const float cst = GAIN * rsqrtf((float)T);
#pragma unroll
    for (int rr = 0; rr < 2; rr++) {
        float s = 0.f;
#pragma unroll
        for (int nt = 0; nt < 8; nt++)
            s += oacc[nt][rr * 2] * oacc[nt][rr * 2] + oacc[nt][rr * 2 + 1] * oacc[nt][rr * 2 + 1];
        s += __shfl_xor_sync(~0u, s, 1);
        s += __shfl_xor_sync(~0u, s, 2);
        const int t = q0 + warp * 16 + g + rr * 8;
        const float n = cst * sqrtf(s);
        const float f = 8.0f * cst * g_mag[b * T + t] / (n + EPS);
        uint32_t* dp = g_att + ((size_t)b * T + t) * Dh + h * (HD / 2);
#pragma unroll
        for (int nt = 0; nt < 8; nt++)
            dp[nt * 4 + c] = h2(oacc[nt][rr * 2] * f, oacc[nt][rr * 2 + 1] * f);
    }
}

// ---------------------------------------------------------------------------
// Kernel 4: out-projection  y = att @ wn_out^T  (fp32 out)
// grid: (768/64, 8192/128)
// ---------------------------------------------------------------------------
__global__ void __launch_bounds__(256) proj_mm(float* __restrict__ out) {
    extern __shared__ __align__(16) uint32_t dsm[];
    const int n0 = blockIdx.x * 64, m0 = blockIdx.y * 128;
    const int tid = threadIdx.x, lane = tid & 31, warp = tid >> 5;
    const int wm = warp >> 1, wn = warp & 1, g = lane >> 2, c = lane & 3;

    float acc[2][4][4] = {};
    gemm_core(g_att, g_wo, m0, n0, dsm, acc, tid);

#pragma unroll
    for (int mt = 0; mt < 2; mt++) {
#pragma unroll
        for (int rr = 0; rr < 2; rr++) {
            const int m = m0 + wm * 32 + mt * 16 + g + rr * 8;
            float* dp = out + (size_t)m * D + n0;
#pragma unroll
            for (int nt = 0; nt < 4; nt++) {
                const int col = wn * 32 + nt * 8 + 2 * c;
                *(float2*)&dp[col] = make_float2(acc[mt][nt][rr * 2],
                                                 acc[mt][nt][rr * 2 + 1]);
            }
        }
    }
}

// ---------------------------------------------------------------------------
extern "C" void kernel_launch(void* const* d_in, const int* in_sizes, int n_in,
                              void* d_out, int out_size) {
    const float* x     = (const float*)d_in[0];
    const float* qkv_w = (const float*)d_in[1];
    const float* out_w = (const float*)d_in[2];

    cudaFuncSetAttribute(qkv_mm, cudaFuncAttributeMaxDynamicSharedMemorySize, GEMM_SMEM);
    cudaFuncSetAttribute(proj_mm, cudaFuncAttributeMaxDynamicSharedMemorySize, GEMM_SMEM);
    cudaFuncSetAttribute(attn_mma, cudaFuncAttributeMaxDynamicSharedMemorySize, ATTN_SMEM);

    prep_kernel<<<NQKV + D + BT, 256>>>(x, qkv_w, out_w);
    qkv_mm<<<dim3(NQKV / 64, BT / 128), 256, GEMM_SMEM>>>();
    attn_mma<<<dim3(T / 128, H, B), 256, ATTN_SMEM>>>();
    proj_mm<<<dim3(D / 64, BT / 128), 256, GEMM_SMEM>>>((float*)d_out);
}

// round 10
// speedup vs baseline: 3.8600x; 1.0593x over previous
#include <cuda_runtime.h>
#include <cuda_fp16.h>
#include <math.h>
#include <stdint.h>

// Problem constants
constexpr int B  = 4;
constexpr int T  = 2048;
constexpr int D  = 768;
constexpr int H  = 12;
constexpr int HD = 64;
constexpr int BT = B * T;          // 8192
constexpr int NQKV = 3 * D;        // 2304
constexpr float EPS  = 1e-4f;
constexpr float GAIN = 1.8402f;

constexpr int Dh   = D / 2;        // 384 uint32 (half2) per row
constexpr int PAD  = 20;           // gemm chunk row stride (16 data + 4 pad u32)
constexpr int APAD = 36;           // attn row stride (32 data + 4 pad u32)
constexpr int KC   = 16;           // gemm k-chunk in uint32 (= 32 halfs)
constexpr int NC   = Dh / KC;      // 24 chunks
constexpr int NCT  = T / 64;       // 32 attention KV chunks

// GEMM 3-stage smem layout (u32 units): 128x128 tile
constexpr int A_U32   = 128 * PAD;           // 2560
constexpr int B_U32   = 128 * PAD;           // 2560
constexpr int STG_U32 = A_U32 + B_U32;       // 5120 (20480 B)
constexpr int GEMM_SMEM = 3 * STG_U32 * 4;   // 61440 B
// Attn 3-stage smem layout
constexpr int AK_U32   = 64 * APAD;          // 2304
constexpr int ASTG_U32 = 2 * AK_U32;         // K+V = 4608 (18432 B)
constexpr int ATTN_SMEM = 3 * ASTG_U32 * 4;  // 55296 B

// Scratch (__device__ globals; fp16 storage packed as uint32 = half2)
__device__ uint32_t g_xh[BT * Dh];
__device__ uint32_t g_wq[NQKV * Dh];
__device__ uint32_t g_wo[D * Dh];
__device__ uint32_t g_Q[B * H * T * (HD / 2)];
__device__ uint32_t g_K[B * H * T * (HD / 2)];
__device__ __half   g_Vt[(size_t)B * H * HD * T];   // V transposed: [b][h][d][t]
__device__ uint32_t g_att[BT * Dh];
__device__ float    g_mag[BT];

__device__ __forceinline__ uint32_t h2(float lo, float hi) {
    uint32_t u;  // first asm source -> upper 16 bits
    asm("cvt.rn.f16x2.f32 %0, %1, %2;" : "=r"(u) : "f"(hi), "f"(lo));
    return u;
}
__device__ __forceinline__ void mma16(float c[4], const uint32_t a[4], const uint32_t b[2]) {
    asm volatile(
        "mma.sync.aligned.m16n8k16.row.col.f32.f16.f16.f32 "
        "{%0,%1,%2,%3}, {%4,%5,%6,%7}, {%8,%9}, {%0,%1,%2,%3};"
        : "+f"(c[0]), "+f"(c[1]), "+f"(c[2]), "+f"(c[3])
        : "r"(a[0]), "r"(a[1]), "r"(a[2]), "r"(a[3]), "r"(b[0]), "r"(b[1]));
}
__device__ __forceinline__ uint32_t saddr(const void* p) {
    return (uint32_t)__cvta_generic_to_shared(p);
}
__device__ __forceinline__ void ldsm4(uint32_t* r, uint32_t a) {
    asm volatile("ldmatrix.sync.aligned.m8n8.x4.shared.b16 {%0,%1,%2,%3}, [%4];"
                 : "=r"(r[0]), "=r"(r[1]), "=r"(r[2]), "=r"(r[3]) : "r"(a));
}
__device__ __forceinline__ void cp16(uint32_t s, const void* g) {
    asm volatile("cp.async.cg.shared.global [%0], [%1], 16;" :: "r"(s), "l"(g));
}
__device__ __forceinline__ void cp_commit() {
    asm volatile("cp.async.commit_group;" ::: "memory");
}
template <int N>
__device__ __forceinline__ void cp_wait() {
    asm volatile("cp.async.wait_group %0;" :: "n"(N) : "memory");
}

// ---------------------------------------------------------------------------
// Kernel 1: weight row-norm -> fp16; x -> fp16 copy + per-token magnitude.
// ---------------------------------------------------------------------------
__global__ void __launch_bounds__(256) prep_kernel(const float* __restrict__ x,
                                                   const float* __restrict__ qkv_w,
                                                   const float* __restrict__ out_w) {
    const int r = blockIdx.x;
    const float* src;
    uint32_t* dst;
    float* magdst = nullptr;
    bool donorm = true;
    if (r < NQKV) {
        src = qkv_w + (size_t)r * D;  dst = g_wq + (size_t)r * Dh;
    } else if (r < NQKV + D) {
        src = out_w + (size_t)(r - NQKV) * D;  dst = g_wo + (size_t)(r - NQKV) * Dh;
    } else {
        const int tr = r - (NQKV + D);
        src = x + (size_t)tr * D;  dst = g_xh + (size_t)tr * Dh;
        magdst = g_mag + tr;  donorm = false;
    }
    const int tid = threadIdx.x;
    float4 f = make_float4(0.f, 0.f, 0.f, 0.f);
    if (tid < 192) f = ((const float4*)src)[tid];
    float s = f.x * f.x + f.y * f.y + f.z * f.z + f.w * f.w;
#pragma unroll
    for (int o = 16; o > 0; o >>= 1) s += __shfl_xor_sync(0xffffffffu, s, o);
    __shared__ float red[8];
    __shared__ float stot;
    if ((tid & 31) == 0) red[tid >> 5] = s;
    __syncthreads();
    if (tid == 0) {
        float t = red[0];
#pragma unroll
        for (int i = 1; i < 8; i++) t += red[i];
        stot = t;
    }
    __syncthreads();
    const float tot = stot;
    if (donorm) {
        const float inv = 1.0f / (sqrtf(tot) + EPS);
        if (tid < 192) {
            dst[2 * tid]     = h2(f.x * inv, f.y * inv);
            dst[2 * tid + 1] = h2(f.z * inv, f.w * inv);
        }
    } else {
        if (tid < 192) {
            dst[2 * tid]     = h2(f.x, f.y);
            dst[2 * tid + 1] = h2(f.z, f.w);
        }
        if (tid == 0) magdst[0] = sqrtf(tot) * (1.0f / sqrtf((float)D));
    }
}

// ---------------------------------------------------------------------------
// fp16 GEMM core: 128x128 tile, 3-stage cp.async, one __syncthreads per chunk.
// 8 warps (4m x 2n), warp tile 32x64 (2 mtiles x 8 ntiles).
// ---------------------------------------------------------------------------
__device__ __forceinline__ void gemm_core(const uint32_t* __restrict__ A,
                                          const uint32_t* __restrict__ W,
                                          int m0, int n0, uint32_t* sm,
                                          float (&acc)[2][8][4], int tid) {
    const int lane = tid & 31, warp = tid >> 5;
    const int wm = warp >> 1, wn = warp & 1;
    const uint32_t* Ab = A + (size_t)m0 * Dh;
    const uint32_t* Wb = W + (size_t)n0 * Dh;
    const uint32_t sb = saddr(sm);

    // ldmatrix offsets relative to a stage base (bytes)
    const uint32_t a_off = ((wm * 32 + (lane & 15)) * PAD + (lane >> 4) * 4) << 2;
    const uint32_t b_off = (A_U32 + (wn * 64 + ((lane >> 4) & 1) * 8 + (lane & 7)) * PAD +
                            ((lane >> 3) & 1) * 4) << 2;

    auto stage = [&](int s, int c) {
        const uint32_t base = sb + (uint32_t)(s * STG_U32) * 4;
        const int k0 = c * KC;
#pragma unroll
        for (int j = 0; j < 2; j++) {            // A: 128 rows x 4 segs of 16B
            const int idx = tid + j * 256;
            const int row = idx >> 2, seg = idx & 3;
            cp16(base + ((row * PAD + seg * 4) << 2), Ab + (size_t)row * Dh + k0 + seg * 4);
        }
#pragma unroll
        for (int j = 0; j < 2; j++) {            // B: 128 rows x 4 segs of 16B
            const int idx = tid + j * 256;
            const int row = idx >> 2, seg = idx & 3;
            cp16(base + ((A_U32 + row * PAD + seg * 4) << 2), Wb + (size_t)row * Dh + k0 + seg * 4);
        }
        cp_commit();
    };

    stage(0, 0);
    stage(1, 1);
    for (int k = 0; k < NC; k++) {
        if (k + 1 < NC) cp_wait<1>(); else cp_wait<0>();
        __syncthreads();
        const uint32_t base = sb + (uint32_t)((k % 3) * STG_U32) * 4;
#pragma unroll
        for (int ks = 0; ks < 2; ks++) {
            const uint32_t kk4 = (ks * 8) << 2;
            uint32_t af[2][4], bq[4][4];
            ldsm4(af[0], base + a_off + kk4);
            ldsm4(af[1], base + a_off + ((16 * PAD) << 2) + kk4);
#pragma unroll
            for (int np = 0; np < 4; np++)
                ldsm4(bq[np], base + b_off + ((np * 16 * PAD) << 2) + kk4);
#pragma unroll
            for (int mt = 0; mt < 2; mt++)
#pragma unroll
                for (int np = 0; np < 4; np++) {
                    mma16(acc[mt][2 * np],     af[mt], bq[np]);
                    mma16(acc[mt][2 * np + 1], af[mt], bq[np] + 2);
                }
        }
        if (k + 2 < NC) stage((k + 2) % 3, k + 2);
    }
}

// ---------------------------------------------------------------------------
// Kernel 2: qkv GEMM + warp-local per-head q/k RMS-normalize + scatter.
// grid: (2304/128, 8192/128). Each warp's 64-wide n-extent == one head.
// ---------------------------------------------------------------------------
__global__ void __launch_bounds__(256, 2) qkv_mm() {
    extern __shared__ __align__(16) uint32_t dsm[];
    const int n0 = blockIdx.x * 128, m0 = blockIdx.y * 128;
    const int tid = threadIdx.x, lane = tid & 31, warp = tid >> 5;
    const int wm = warp >> 1, wn = warp & 1, g = lane >> 2, c = lane & 3;

    float acc[2][8][4] = {};
    gemm_core(g_xh, g_wq, m0, n0, dsm, acc, tid);

    const int which = n0 / D;                      // 0=q 1=k 2=v
    const int head = ((n0 % D) >> 6) + wn;         // warp owns one full head
    const int b = m0 / T;

    if (which < 2) {
        uint32_t* dstb = (which == 0) ? g_Q : g_K;
#pragma unroll
        for (int mt = 0; mt < 2; mt++) {
            float s0 = 0.f, s1 = 0.f;
#pragma unroll
            for (int nt = 0; nt < 8; nt++) {
                s0 += acc[mt][nt][0] * acc[mt][nt][0] + acc[mt][nt][1] * acc[mt][nt][1];
                s1 += acc[mt][nt][2] * acc[mt][nt][2] + acc[mt][nt][3] * acc[mt][nt][3];
            }
            s0 += __shfl_xor_sync(~0u, s0, 1); s0 += __shfl_xor_sync(~0u, s0, 2);
            s1 += __shfl_xor_sync(~0u, s1, 1); s1 += __shfl_xor_sync(~0u, s1, 2);
            const float sc[2] = {8.0f / (sqrtf(s0) + EPS), 8.0f / (sqrtf(s1) + EPS)};
#pragma unroll
            for (int rr = 0; rr < 2; rr++) {
                const int t = (m0 + wm * 32 + mt * 16 + g + rr * 8) & (T - 1);
                uint32_t* dp = dstb + (((size_t)(b * H + head)) * T + t) * (HD / 2);
#pragma unroll
                for (int nt = 0; nt < 8; nt++)
                    dp[nt * 4 + c] = h2(acc[mt][nt][rr * 2] * sc[rr],
                                        acc[mt][nt][rr * 2 + 1] * sc[rr]);
            }
        }
    } else {
        // V: store transposed [d][t] halves
        __half* vbp = g_Vt + ((size_t)(b * H + head)) * HD * T;
#pragma unroll
        for (int mt = 0; mt < 2; mt++) {
#pragma unroll
            for (int rr = 0; rr < 2; rr++) {
                const int t = (m0 + wm * 32 + mt * 16 + g + rr * 8) & (T - 1);
#pragma unroll
                for (int nt = 0; nt < 8; nt++) {
                    const int d = nt * 8 + 2 * c;
                    vbp[(size_t)d * T + t]       = __float2half(acc[mt][nt][rr * 2]);
                    vbp[(size_t)(d + 1) * T + t] = __float2half(acc[mt][nt][rr * 2 + 1]);
                }
            }
        }
    }
}

// ---------------------------------------------------------------------------
// Kernel 3: fused sigmoid attention, 3-stage cp.async, f16x2 tanh sigmoid.
// Block: 128 q-rows, 8 warps (16 rows x 64 cols). Q frags in registers.
// grid: (T/128, H, B). 55296 B dynamic smem.
// ---------------------------------------------------------------------------
__global__ void __launch_bounds__(256) attn_mma() {
    extern __shared__ __align__(16) uint32_t dsm[];
    const int tid = threadIdx.x, lane = tid & 31, warp = tid >> 5;
    const int g = lane >> 2, c = lane & 3;
    const int q0 = blockIdx.x * 128;
    const int h = blockIdx.y, b = blockIdx.z;
    const size_t bh = ((size_t)(b * H + h)) * T;

    // Q fragments (16 rows x 64 k = 4 k-steps), persistent in registers
    uint32_t qf[4][4];
    {
        const uint32_t* Qg = g_Q + (bh + q0 + warp * 16) * (HD / 2);
#pragma unroll
        for (int ks = 0; ks < 4; ks++) {
            qf[ks][0] = Qg[(size_t)g * 32 + ks * 8 + c];
            qf[ks][1] = Qg[(size_t)(g + 8) * 32 + ks * 8 + c];
            qf[ks][2] = Qg[(size_t)g * 32 + ks * 8 + c + 4];
            qf[ks][3] = Qg[(size_t)(g + 8) * 32 + ks * 8 + c + 4];
        }
    }

    const uint32_t sb = saddr(dsm);
    const uint32_t krow = ((lane >> 4) & 1) * 8 + (lane & 7);
    const uint32_t kcol = ((lane >> 3) & 1) * 4;
    const uint32_t kb_off = (krow * APAD + kcol) << 2;
    const uint32_t vb_off = ((AK_U32 + krow * APAD + kcol)) << 2;

    const uint32_t* Kg0  = g_K + bh * (HD / 2);
    const uint32_t* Vtg0 = (const uint32_t*)(g_Vt + bh * HD);  // rows of T/2 uint32

    auto stage_kv = [&](int s, int i) {
        const uint32_t base = sb + (uint32_t)(s * ASTG_U32) * 4;
        const int s0 = i * 64, sc0 = s0 >> 1;
#pragma unroll
        for (int j = 0; j < 2; j++) {
            const int idx = tid + j * 256;
            const int row = idx >> 3, seg = idx & 7;
            cp16(base + ((row * APAD + seg * 4) << 2),
                 Kg0 + (size_t)(s0 + row) * 32 + seg * 4);
            cp16(base + ((AK_U32 + row * APAD + seg * 4) << 2),
                 Vtg0 + (size_t)row * (T / 2) + sc0 + seg * 4);
        }
        cp_commit();
    };

    float oacc[8][4] = {};
    constexpr float S16 = 0.0625f;                 // 1/16 (sigmoid(s/8)=.5tanh(s/16)+.5)

    stage_kv(0, 0);
    stage_kv(1, 1);
    for (int i = 0; i < NCT; i++) {
        if (i + 1 < NCT) cp_wait<1>(); else cp_wait<0>();
        __syncthreads();
        const uint32_t base = sb + (uint32_t)((i % 3) * ASTG_U32) * 4;

        // S = Q K^T  (16 x 64 per warp), 4 ks x 8 nt
        float sacc[8][4] = {};
#pragma unroll
        for (int ks = 0; ks < 4; ks++) {
            uint32_t bq[4][4];
#pragma unroll
            for (int np = 0; np < 4; np++)
                ldsm4(bq[np], base + kb_off + ((np * 16 * APAD + ks * 8) << 2));
#pragma unroll
            for (int np = 0; np < 4; np++) {
                mma16(sacc[2 * np],     qf[ks], bq[np]);
                mma16(sacc[2 * np + 1], qf[ks], bq[np] + 2);
            }
        }

        // O += sigmoid(S/8) V : sigmoid in f16x2 (half MUFU count), A-frags direct
#pragma unroll
        for (int kt = 0; kt < 4; kt++) {
            uint32_t af[4];
            af[0] = h2(sacc[2 * kt][0] * S16,     sacc[2 * kt][1] * S16);
            af[1] = h2(sacc[2 * kt][2] * S16,     sacc[2 * kt][3] * S16);
            af[2] = h2(sacc[2 * kt + 1][0] * S16, sacc[2 * kt + 1][1] * S16);
            af[3] = h2(sacc[2 * kt + 1][2] * S16, sacc[2 * kt + 1][3] * S16);
#pragma unroll
            for (int j = 0; j < 4; j++) {
                asm("tanh.approx.f16x2 %0, %0;" : "+r"(af[j]));
                asm("fma.rn.f16x2 %0, %0, %1, %1;" : "+r"(af[j]) : "r"(0x38003800u));
            }
            uint32_t bq[4][4];
#pragma unroll
            for (int np = 0; np < 4; np++)
                ldsm4(bq[np], base + vb_off + ((np * 16 * APAD + kt * 8) << 2));
#pragma unroll
            for (int np = 0; np < 4; np++) {
                mma16(oacc[2 * np],     af, bq[np]);
                mma16(oacc[2 * np + 1], af, bq[np] + 2);
            }
        }
        if (i + 2 < NCT) stage_kv((i + 2) % 3, i + 2);
    }

    // Epilogue: out = mag * 8*cst*acc / (cst*||acc|| + eps), half2-packed
    const float cst = GAIN * rsqrtf((float)T);
#pragma unroll
    for (int rr = 0; rr < 2; rr++) {
        float s = 0.f;
#pragma unroll
        for (int nt = 0; nt < 8; nt++)
            s += oacc[nt][rr * 2] * oacc[nt][rr * 2] + oacc[nt][rr * 2 + 1] * oacc[nt][rr * 2 + 1];
        s += __shfl_xor_sync(~0u, s, 1);
        s += __shfl_xor_sync(~0u, s, 2);
        const int t = q0 + warp * 16 + g + rr * 8;
        const float n = cst * sqrtf(s);
        const float f = 8.0f * cst * g_mag[b * T + t] / (n + EPS);
        uint32_t* dp = g_att + ((size_t)b * T + t) * Dh + h * (HD / 2);
#pragma unroll
        for (int nt = 0; nt < 8; nt++)
            dp[nt * 4 + c] = h2(oacc[nt][rr * 2] * f, oacc[nt][rr * 2 + 1] * f);
    }
}

// ---------------------------------------------------------------------------
// Kernel 4: out-projection  y = att @ wn_out^T  (fp32 out)
// grid: (768/128, 8192/128)
// ---------------------------------------------------------------------------
__global__ void __launch_bounds__(256, 2) proj_mm(float* __restrict__ out) {
    extern __shared__ __align__(16) uint32_t dsm[];
    const int n0 = blockIdx.x * 128, m0 = blockIdx.y * 128;
    const int tid = threadIdx.x, lane = tid & 31, warp = tid >> 5;
    const int wm = warp >> 1, wn = warp & 1, g = lane >> 2, c = lane & 3;

    float acc[2][8][4] = {};
    gemm_core(g_att, g_wo, m0, n0, dsm, acc, tid);

#pragma unroll
    for (int mt = 0; mt < 2; mt++) {
#pragma unroll
        for (int rr = 0; rr < 2; rr++) {
            const int m = m0 + wm * 32 + mt * 16 + g + rr * 8;
            float* dp = out + (size_t)m * D + n0 + wn * 64;
#pragma unroll
            for (int nt = 0; nt < 8; nt++) {
                const int col = nt * 8 + 2 * c;
                *(float2*)&dp[col] = make_float2(acc[mt][nt][rr * 2],
                                                 acc[mt][nt][rr * 2 + 1]);
            }
        }
    }
}

// ---------------------------------------------------------------------------
extern "C" void kernel_launch(void* const* d_in, const int* in_sizes, int n_in,
                              void* d_out, int out_size) {
    const float* x     = (const float*)d_in[0];
    const float* qkv_w = (const float*)d_in[1];
    const float* out_w = (const float*)d_in[2];

    cudaFuncSetAttribute(qkv_mm, cudaFuncAttributeMaxDynamicSharedMemorySize, GEMM_SMEM);
    cudaFuncSetAttribute(proj_mm, cudaFuncAttributeMaxDynamicSharedMemorySize, GEMM_SMEM);
    cudaFuncSetAttribute(attn_mma, cudaFuncAttributeMaxDynamicSharedMemorySize, ATTN_SMEM);

    prep_kernel<<<NQKV + D + BT, 256>>>(x, qkv_w, out_w);
    qkv_mm<<<dim3(NQKV / 128, BT / 128), 256, GEMM_SMEM>>>();
    attn_mma<<<dim3(T / 128, H, B), 256, ATTN_SMEM>>>();
    proj_mm<<<dim3(D / 128, BT / 128), 256, GEMM_SMEM>>>((float*)d_out);
}

// round 11
// speedup vs baseline: 3.9651x; 1.0272x over previous
#include <cuda_runtime.h>
#include <cuda_fp16.h>
#include <math.h>
#include <stdint.h>

// Problem constants
constexpr int B  = 4;
constexpr int T  = 2048;
constexpr int D  = 768;
constexpr int H  = 12;
constexpr int HD = 64;
constexpr int BT = B * T;          // 8192
constexpr int NQKV = 3 * D;        // 2304
constexpr float EPS  = 1e-4f;
constexpr float GAIN = 1.8402f;

constexpr int Dh   = D / 2;        // 384 uint32 (half2) per row

// GEMM: 128x128 tile, 64-half chunks (32 u32), 2-stage pipeline
constexpr int PADG = 36;           // 32 data + 4 pad u32
constexpr int KC2  = 32;           // chunk size in u32
constexpr int NC2  = Dh / KC2;     // 12 chunks
constexpr int A2_U32   = 128 * PADG;        // 4608
constexpr int STG2_U32 = 2 * A2_U32;        // 9216 (36864 B)
constexpr int GEMM_SMEM = 2 * STG2_U32 * 4; // 73728 B

// Attn: 128-key stages (two 64-key compute halves), 2-stage pipeline
constexpr int AK2   = 128 * 36;             // K tile: 128 keys x (32+4) u32
constexpr int AV2   = 64 * 68;              // Vt tile: 64 d x (64+4) u32
constexpr int ASTG2 = AK2 + AV2;            // 8960 u32 (35840 B)
constexpr int ATTN_SMEM = 2 * ASTG2 * 4;    // 71680 B
constexpr int NCT2  = T / 128;              // 16 stages

// Scratch (__device__ globals; fp16 storage packed as uint32 = half2)
__device__ uint32_t g_xh[BT * Dh];
__device__ uint32_t g_wq[NQKV * Dh];
__device__ uint32_t g_wo[D * Dh];
__device__ uint32_t g_Q[B * H * T * (HD / 2)];
__device__ uint32_t g_K[B * H * T * (HD / 2)];
__device__ __half   g_Vt[(size_t)B * H * HD * T];   // V transposed: [b][h][d][t]
__device__ uint32_t g_att[BT * Dh];
__device__ float    g_mag[BT];

__device__ __forceinline__ uint32_t h2(float lo, float hi) {
    uint32_t u;  // first asm source -> upper 16 bits
    asm("cvt.rn.f16x2.f32 %0, %1, %2;" : "=r"(u) : "f"(hi), "f"(lo));
    return u;
}
__device__ __forceinline__ void mma16(float c[4], const uint32_t a[4], const uint32_t b[2]) {
    asm volatile(
        "mma.sync.aligned.m16n8k16.row.col.f32.f16.f16.f32 "
        "{%0,%1,%2,%3}, {%4,%5,%6,%7}, {%8,%9}, {%0,%1,%2,%3};"
        : "+f"(c[0]), "+f"(c[1]), "+f"(c[2]), "+f"(c[3])
        : "r"(a[0]), "r"(a[1]), "r"(a[2]), "r"(a[3]), "r"(b[0]), "r"(b[1]));
}
__device__ __forceinline__ uint32_t saddr(const void* p) {
    return (uint32_t)__cvta_generic_to_shared(p);
}
__device__ __forceinline__ void ldsm4(uint32_t* r, uint32_t a) {
    asm volatile("ldmatrix.sync.aligned.m8n8.x4.shared.b16 {%0,%1,%2,%3}, [%4];"
                 : "=r"(r[0]), "=r"(r[1]), "=r"(r[2]), "=r"(r[3]) : "r"(a));
}
__device__ __forceinline__ void cp16(uint32_t s, const void* g) {
    asm volatile("cp.async.cg.shared.global [%0], [%1], 16;" :: "r"(s), "l"(g));
}
__device__ __forceinline__ void cp_commit() {
    asm volatile("cp.async.commit_group;" ::: "memory");
}
template <int N>
__device__ __forceinline__ void cp_wait() {
    asm volatile("cp.async.wait_group %0;" :: "n"(N) : "memory");
}

// ---------------------------------------------------------------------------
// Kernel 1: warp-per-row. weight row-norm -> fp16; x -> fp16 + magnitude.
// 8 rows per 256-thread block; pure warp-shuffle reduction (no barriers).
// ---------------------------------------------------------------------------
__global__ void __launch_bounds__(256) prep_kernel(const float* __restrict__ x,
                                                   const float* __restrict__ qkv_w,
                                                   const float* __restrict__ out_w) {
    const int row = blockIdx.x * 8 + (threadIdx.x >> 5);
    const int lane = threadIdx.x & 31;
    const float* src;
    uint32_t* dst;
    float* magdst = nullptr;
    bool donorm = true;
    if (row < NQKV) {
        src = qkv_w + (size_t)row * D;  dst = g_wq + (size_t)row * Dh;
    } else if (row < NQKV + D) {
        src = out_w + (size_t)(row - NQKV) * D;  dst = g_wo + (size_t)(row - NQKV) * Dh;
    } else {
        const int tr = row - (NQKV + D);
        src = x + (size_t)tr * D;  dst = g_xh + (size_t)tr * Dh;
        magdst = g_mag + tr;  donorm = false;
    }
    float4 v[6];
    float s = 0.f;
#pragma unroll
    for (int j = 0; j < 6; j++) {
        v[j] = ((const float4*)src)[lane + j * 32];
        s += v[j].x * v[j].x + v[j].y * v[j].y + v[j].z * v[j].z + v[j].w * v[j].w;
    }
#pragma unroll
    for (int o = 16; o > 0; o >>= 1) s += __shfl_xor_sync(0xffffffffu, s, o);
    if (donorm) {
        const float inv = 1.0f / (sqrtf(s) + EPS);
#pragma unroll
        for (int j = 0; j < 6; j++) {
            dst[2 * (lane + j * 32)]     = h2(v[j].x * inv, v[j].y * inv);
            dst[2 * (lane + j * 32) + 1] = h2(v[j].z * inv, v[j].w * inv);
        }
    } else {
#pragma unroll
        for (int j = 0; j < 6; j++) {
            dst[2 * (lane + j * 32)]     = h2(v[j].x, v[j].y);
            dst[2 * (lane + j * 32) + 1] = h2(v[j].z, v[j].w);
        }
        if (lane == 0) magdst[0] = sqrtf(s) * (1.0f / sqrtf((float)D));
    }
}

// ---------------------------------------------------------------------------
// fp16 GEMM core: 128x128 tile, 64-half chunks, 2-stage cp.async pipeline.
// 8 warps (4m x 2n), warp tile 32x64. One __syncthreads per chunk (12 total).
// ---------------------------------------------------------------------------
__device__ __forceinline__ void gemm_core(const uint32_t* __restrict__ A,
                                          const uint32_t* __restrict__ W,
                                          int m0, int n0, uint32_t* sm,
                                          float (&acc)[2][8][4], int tid) {
    const int lane = tid & 31, warp = tid >> 5;
    const int wm = warp >> 1, wn = warp & 1;
    const uint32_t* Ab = A + (size_t)m0 * Dh;
    const uint32_t* Wb = W + (size_t)n0 * Dh;
    const uint32_t sb = saddr(sm);

    const uint32_t a_off = ((wm * 32 + (lane & 15)) * PADG + (lane >> 4) * 4) << 2;
    const uint32_t b_off = (A2_U32 + (wn * 64 + ((lane >> 4) & 1) * 8 + (lane & 7)) * PADG +
                            ((lane >> 3) & 1) * 4) << 2;

    auto stage = [&](int s, int c) {
        const uint32_t base = sb + (uint32_t)(s * STG2_U32) * 4;
        const int k0 = c * KC2;
#pragma unroll
        for (int j = 0; j < 4; j++) {            // A: 128 rows x 8 segs of 16B
            const int idx = tid + j * 256;
            const int row = idx >> 3, seg = idx & 7;
            cp16(base + ((row * PADG + seg * 4) << 2), Ab + (size_t)row * Dh + k0 + seg * 4);
        }
#pragma unroll
        for (int j = 0; j < 4; j++) {            // B: 128 rows x 8 segs of 16B
            const int idx = tid + j * 256;
            const int row = idx >> 3, seg = idx & 7;
            cp16(base + ((A2_U32 + row * PADG + seg * 4) << 2), Wb + (size_t)row * Dh + k0 + seg * 4);
        }
        cp_commit();
    };

    stage(0, 0);
    for (int k = 0; k < NC2; k++) {
        cp_wait<0>();
        __syncthreads();
        if (k + 1 < NC2) stage((k + 1) & 1, k + 1);   // overlaps compute below
        const uint32_t base = sb + (uint32_t)((k & 1) * STG2_U32) * 4;
#pragma unroll
        for (int ks = 0; ks < 4; ks++) {
            const uint32_t kk4 = (ks * 8) << 2;
            uint32_t af[2][4], bq[4][4];
            ldsm4(af[0], base + a_off + kk4);
            ldsm4(af[1], base + a_off + ((16 * PADG) << 2) + kk4);
#pragma unroll
            for (int np = 0; np < 4; np++)
                ldsm4(bq[np], base + b_off + ((np * 16 * PADG) << 2) + kk4);
#pragma unroll
            for (int mt = 0; mt < 2; mt++)
#pragma unroll
                for (int np = 0; np < 4; np++) {
                    mma16(acc[mt][2 * np],     af[mt], bq[np]);
                    mma16(acc[mt][2 * np + 1], af[mt], bq[np] + 2);
                }
        }
    }
}

// ---------------------------------------------------------------------------
// Kernel 2: qkv GEMM + warp-local per-head q/k RMS-normalize + scatter.
// V path transposes through SMEM for coalesced g_Vt writes.
// grid: (2304/128, 8192/128). Each warp's 64-wide n-extent == one head.
// ---------------------------------------------------------------------------
__global__ void __launch_bounds__(256, 2) qkv_mm() {
    extern __shared__ __align__(16) uint32_t dsm[];
    const int n0 = blockIdx.x * 128, m0 = blockIdx.y * 128;
    const int tid = threadIdx.x, lane = tid & 31, warp = tid >> 5;
    const int wm = warp >> 1, wn = warp & 1, g = lane >> 2, c = lane & 3;

    float acc[2][8][4] = {};
    gemm_core(g_xh, g_wq, m0, n0, dsm, acc, tid);

    const int which = n0 / D;                      // 0=q 1=k 2=v
    const int headbase = (n0 % D) >> 6;
    const int b = m0 / T;

    if (which < 2) {
        const int head = headbase + wn;
        uint32_t* dstb = (which == 0) ? g_Q : g_K;
#pragma unroll
        for (int mt = 0; mt < 2; mt++) {
            float s0 = 0.f, s1 = 0.f;
#pragma unroll
            for (int nt = 0; nt < 8; nt++) {
                s0 += acc[mt][nt][0] * acc[mt][nt][0] + acc[mt][nt][1] * acc[mt][nt][1];
                s1 += acc[mt][nt][2] * acc[mt][nt][2] + acc[mt][nt][3] * acc[mt][nt][3];
            }
            s0 += __shfl_xor_sync(~0u, s0, 1); s0 += __shfl_xor_sync(~0u, s0, 2);
            s1 += __shfl_xor_sync(~0u, s1, 1); s1 += __shfl_xor_sync(~0u, s1, 2);
            const float sc[2] = {8.0f / (sqrtf(s0) + EPS), 8.0f / (sqrtf(s1) + EPS)};
#pragma unroll
            for (int rr = 0; rr < 2; rr++) {
                const int t = (m0 + wm * 32 + mt * 16 + g + rr * 8) & (T - 1);
                uint32_t* dp = dstb + (((size_t)(b * H + head)) * T + t) * (HD / 2);
#pragma unroll
                for (int nt = 0; nt < 8; nt++)
                    dp[nt * 4 + c] = h2(acc[mt][nt][rr * 2] * sc[rr],
                                        acc[mt][nt][rr * 2 + 1] * sc[rr]);
            }
        }
    } else {
        // V: transpose via smem, then coalesced 128B row writes to g_Vt.
        __syncthreads();                           // last chunk's ldsm reads done
        __half* Vsm = (__half*)dsm;                // [128 d][136 halfs]
#pragma unroll
        for (int mt = 0; mt < 2; mt++)
#pragma unroll
            for (int rr = 0; rr < 2; rr++) {
                const int tl = wm * 32 + mt * 16 + g + rr * 8;
#pragma unroll
                for (int nt = 0; nt < 8; nt++) {
                    const int d0 = wn * 64 + nt * 8 + 2 * c;
                    Vsm[d0 * 136 + tl]       = __float2half(acc[mt][nt][rr * 2]);
                    Vsm[(d0 + 1) * 136 + tl] = __float2half(acc[mt][nt][rr * 2 + 1]);
                }
            }
        __syncthreads();
        const int col = tid & 127;                 // d_local
        const int hf = tid >> 7;                   // t half
        const int head = headbase + (col >> 6);
        const int dd = col & 63;
        const int t0 = (m0 & (T - 1)) + hf * 64;
        const uint4* srcv = (const uint4*)(Vsm + col * 136 + hf * 64);
        uint4* dstv = (uint4*)(g_Vt + ((size_t)(b * H + head) * HD + dd) * T + t0);
#pragma unroll
        for (int j = 0; j < 8; j++) dstv[j] = srcv[j];
    }
}

// ---------------------------------------------------------------------------
// Kernel 3: fused sigmoid attention. 128-key 2-stage pipeline, two 64-key
// compute halves per stage (16 barriers total). f16x2 tanh sigmoid.
// grid: (T/128, H, B). 71680 B dynamic smem.
// ---------------------------------------------------------------------------
__global__ void __launch_bounds__(256) attn_mma() {
    extern __shared__ __align__(16) uint32_t dsm[];
    const int tid = threadIdx.x, lane = tid & 31, warp = tid >> 5;
    const int g = lane >> 2, c = lane & 3;
    const int q0 = blockIdx.x * 128;
    const int h = blockIdx.y, b = blockIdx.z;
    const size_t bh = ((size_t)(b * H + h)) * T;

    // Q fragments (16 rows x 64 k = 4 k-steps), persistent in registers
    uint32_t qf[4][4];
    {
        const uint32_t* Qg = g_Q + (bh + q0 + warp * 16) * (HD / 2);
#pragma unroll
        for (int ks = 0; ks < 4; ks++) {
            qf[ks][0] = Qg[(size_t)g * 32 + ks * 8 + c];
            qf[ks][1] = Qg[(size_t)(g + 8) * 32 + ks * 8 + c];
            qf[ks][2] = Qg[(size_t)g * 32 + ks * 8 + c + 4];
            qf[ks][3] = Qg[(size_t)(g + 8) * 32 + ks * 8 + c + 4];
        }
    }

    const uint32_t sb = saddr(dsm);
    const uint32_t krow = ((lane >> 4) & 1) * 8 + (lane & 7);
    const uint32_t kcol = ((lane >> 3) & 1) * 4;
    const uint32_t kb_off = (krow * 36 + kcol) << 2;
    const uint32_t vb_off = (AK2 + krow * 68 + kcol) << 2;

    const uint32_t* Kg0  = g_K + bh * (HD / 2);
    const uint32_t* Vtg0 = (const uint32_t*)(g_Vt + bh * HD);  // rows of T/2 uint32

    auto stage_kv = [&](int s, int i) {
        const uint32_t base = sb + (uint32_t)(s * ASTG2) * 4;
#pragma unroll
        for (int j = 0; j < 4; j++) {              // K: 128 rows x 8 segs
            const int idx = tid + j * 256;
            const int row = idx >> 3, seg = idx & 7;
            cp16(base + ((row * 36 + seg * 4) << 2),
                 Kg0 + (size_t)(i * 128 + row) * 32 + seg * 4);
        }
#pragma unroll
        for (int j = 0; j < 4; j++) {              // Vt: 64 rows x 16 segs
            const int idx = tid + j * 256;
            const int row = idx >> 4, seg = idx & 15;
            cp16(base + ((AK2 + row * 68 + seg * 4) << 2),
                 Vtg0 + (size_t)row * (T / 2) + i * 64 + seg * 4);
        }
        cp_commit();
    };

    float oacc[8][4] = {};
    constexpr float S16 = 0.0625f;                 // sigmoid(s/8)=.5tanh(s/16)+.5

    stage_kv(0, 0);
    for (int i = 0; i < NCT2; i++) {
        cp_wait<0>();
        __syncthreads();
        if (i + 1 < NCT2) stage_kv((i + 1) & 1, i + 1);
        const uint32_t base = sb + (uint32_t)((i & 1) * ASTG2) * 4;

#pragma unroll
        for (int hh = 0; hh < 2; hh++) {
            // S = Q K^T  (16 x 64 per warp)
            float sacc[8][4] = {};
#pragma unroll
            for (int ks = 0; ks < 4; ks++) {
                uint32_t bq[4][4];
#pragma unroll
                for (int np = 0; np < 4; np++)
                    ldsm4(bq[np], base + kb_off + (((hh * 64 + np * 16) * 36 + ks * 8) << 2));
#pragma unroll
                for (int np = 0; np < 4; np++) {
                    mma16(sacc[2 * np],     qf[ks], bq[np]);
                    mma16(sacc[2 * np + 1], qf[ks], bq[np] + 2);
                }
            }
            // O += sigmoid(S/8) V  (f16x2 sigmoid, A-frags direct)
#pragma unroll
            for (int kt = 0; kt < 4; kt++) {
                uint32_t af[4];
                af[0] = h2(sacc[2 * kt][0] * S16,     sacc[2 * kt][1] * S16);
                af[1] = h2(sacc[2 * kt][2] * S16,     sacc[2 * kt][3] * S16);
                af[2] = h2(sacc[2 * kt + 1][0] * S16, sacc[2 * kt + 1][1] * S16);
                af[3] = h2(sacc[2 * kt + 1][2] * S16, sacc[2 * kt + 1][3] * S16);
#pragma unroll
                for (int j = 0; j < 4; j++) {
                    asm("tanh.approx.f16x2 %0, %0;" : "+r"(af[j]));
                    asm("fma.rn.f16x2 %0, %0, %1, %1;" : "+r"(af[j]) : "r"(0x38003800u));
                }
                uint32_t bq[4][4];
#pragma unroll
                for (int np = 0; np < 4; np++)
                    ldsm4(bq[np], base + vb_off + ((np * 16 * 68 + hh * 32 + kt * 8) << 2));
#pragma unroll
                for (int np = 0; np < 4; np++) {
                    mma16(oacc[2 * np],     af, bq[np]);
                    mma16(oacc[2 * np + 1], af, bq[np] + 2);
                }
            }
        }
    }

    // Epilogue: out = mag * 8*cst*acc / (cst*||acc|| + eps), half2-packed
    const float cst = GAIN * rsqrtf((float)T);
#pragma unroll
    for (int rr = 0; rr < 2; rr++) {
        float s = 0.f;
#pragma unroll
        for (int nt = 0; nt < 8; nt++)
            s += oacc[nt][rr * 2] * oacc[nt][rr * 2] + oacc[nt][rr * 2 + 1] * oacc[nt][rr * 2 + 1];
        s += __shfl_xor_sync(~0u, s, 1);
        s += __shfl_xor_sync(~0u, s, 2);
        const int t = q0 + warp * 16 + g + rr * 8;
        const float n = cst * sqrtf(s);
        const float f = 8.0f * cst * g_mag[b * T + t] / (n + EPS);
        uint32_t* dp = g_att + ((size_t)b * T + t) * Dh + h * (HD / 2);
#pragma unroll
        for (int nt = 0; nt < 8; nt++)
            dp[nt * 4 + c] = h2(oacc[nt][rr * 2] * f, oacc[nt][rr * 2 + 1] * f);
    }
}

// ---------------------------------------------------------------------------
// Kernel 4: out-projection  y = att @ wn_out^T  (fp32 out)
// grid: (768/128, 8192/128)
// ---------------------------------------------------------------------------
__global__ void __launch_bounds__(256, 2) proj_mm(float* __restrict__ out) {
    extern __shared__ __align__(16) uint32_t dsm[];
    const int n0 = blockIdx.x * 128, m0 = blockIdx.y * 128;
    const int tid = threadIdx.x, lane = tid & 31, warp = tid >> 5;
    const int wm = warp >> 1, wn = warp & 1, g = lane >> 2, c = lane & 3;

    float acc[2][8][4] = {};
    gemm_core(g_att, g_wo, m0, n0, dsm, acc, tid);

#pragma unroll
    for (int mt = 0; mt < 2; mt++) {
#pragma unroll
        for (int rr = 0; rr < 2; rr++) {
            const int m = m0 + wm * 32 + mt * 16 + g + rr * 8;
            float* dp = out + (size_t)m * D + n0 + wn * 64;
#pragma unroll
            for (int nt = 0; nt < 8; nt++) {
                const int col = nt * 8 + 2 * c;
                *(float2*)&dp[col] = make_float2(acc[mt][nt][rr * 2],
                                                 acc[mt][nt][rr * 2 + 1]);
            }
        }
    }
}

// ---------------------------------------------------------------------------
extern "C" void kernel_launch(void* const* d_in, const int* in_sizes, int n_in,
                              void* d_out, int out_size) {
    const float* x     = (const float*)d_in[0];
    const float* qkv_w = (const float*)d_in[1];
    const float* out_w = (const float*)d_in[2];

    cudaFuncSetAttribute(qkv_mm, cudaFuncAttributeMaxDynamicSharedMemorySize, GEMM_SMEM);
    cudaFuncSetAttribute(proj_mm, cudaFuncAttributeMaxDynamicSharedMemorySize, GEMM_SMEM);
    cudaFuncSetAttribute(attn_mma, cudaFuncAttributeMaxDynamicSharedMemorySize, ATTN_SMEM);

    prep_kernel<<<(NQKV + D + BT) / 8, 256>>>(x, qkv_w, out_w);
    qkv_mm<<<dim3(NQKV / 128, BT / 128), 256, GEMM_SMEM>>>();
    attn_mma<<<dim3(T / 128, H, B), 256, ATTN_SMEM>>>();
    proj_mm<<<dim3(D / 128, BT / 128), 256, GEMM_SMEM>>>((float*)d_out);
}